// round 8
// baseline (speedup 1.0000x reference)
#include <cuda_runtime.h>
#include <cuda_fp16.h>
#include <cstdint>
#include <math.h>

#define BATCH 262144
#define GD 16
#define HID 256
#define RR 16
#define ZD 128
#define MTILE 64
#define NBLK (BATCH / MTILE)

// ---- mlp dynamic smem layout (bytes) ----
#define OFF_XF   0        // x A-frags: 4rb x 32lane x 16B = 2048
#define OFF_W1F  2048     // W1 B-frags: 1024 slots x 8B = 8192
#define OFF_W3F  10240    // W3 B-frags: 1024 slots x 8B = 8192
#define OFF_H1F  18432    // h1 A-frags 32768 (h2 frags overlay after GEMM2)
#define OFF_RING 51200    // W2 ring 3 x 16384 = 49152 (GEMM3 partials overlay)
#define SMEM_BYTES 100352

// ---- dyn dynamic smem layout (floats) ----
#define DOFF_ZS  0        // 64*132 = 8448
#define DOFF_CS  8448     // 64*20  = 1280
#define DOFF_LG  9728     // 64
#define DOFF_UFA 9792     // 2048 (16kk x 2nt x 32lane float2)
#define DOFF_UFB 11840    // 2048 (2ks x 16nt x 32lane float2)
#define DYN_SMEM_FLOATS 13888   // 55552 bytes

// scratch (device globals: allocation-free)
__device__ float g_lamg[BATCH];
__device__ float g_d[BATCH * RR];
// fp16 fragment images: W2 8 chunks x 16KB @u32 0, W1 @u32 32768, W3 @u32 34816
__device__ __align__(256) uint32_t g_wfrag[36864];
// tf32 U fragment images (fp32): ufA 2048 f, ufB 2048 f
__device__ __align__(256) float g_ufA[2048];
__device__ __align__(256) float g_ufB[2048];

__device__ __forceinline__ uint32_t fbits(float x) { return __float_as_uint(x); }
__device__ __forceinline__ float nan0(float v) { return isfinite(v) ? v : 0.f; }
__device__ __forceinline__ float silu_f(float x) { return x * (1.f / (1.f + __expf(-x))); }
__device__ __forceinline__ uint32_t packh(float lo, float hi) {
    uint32_t u;
    asm("cvt.rn.f16x2.f32 %0, %1, %2;" : "=r"(u) : "f"(hi), "f"(lo));
    return u;
}
__device__ __forceinline__ uint32_t smem_u32(const void* p) {
    uint32_t a;
    asm("{ .reg .u64 t; cvta.to.shared.u64 t, %1; cvt.u32.u64 %0, t; }" : "=r"(a) : "l"(p));
    return a;
}
__device__ __forceinline__ void cpa16(uint32_t saddr, const void* g) {
    asm volatile("cp.async.cg.shared.global [%0], [%1], 16;\n" ::"r"(saddr), "l"(g));
}
__device__ __forceinline__ void cpcommit() { asm volatile("cp.async.commit_group;\n"); }
template <int N>
__device__ __forceinline__ void cpwait() { asm volatile("cp.async.wait_group %0;\n" ::"n"(N)); }

// fp16 mma m16n8k16, fp32 accumulate
__device__ __forceinline__ void mma16(float d[4], const uint32_t a[4],
                                      const uint32_t b[2], const float c[4]) {
    asm volatile(
        "mma.sync.aligned.m16n8k16.row.col.f32.f16.f16.f32 "
        "{%0,%1,%2,%3}, {%4,%5,%6,%7}, {%8,%9}, {%10,%11,%12,%13};\n"
        : "=f"(d[0]), "=f"(d[1]), "=f"(d[2]), "=f"(d[3])
        : "r"(a[0]), "r"(a[1]), "r"(a[2]), "r"(a[3]),
          "r"(b[0]), "r"(b[1]),
          "f"(c[0]), "f"(c[1]), "f"(c[2]), "f"(c[3]));
}
// tf32 mma m16n8k8 (dyn kernel)
__device__ __forceinline__ void mma8(float d[4], const uint32_t a[4],
                                     const uint32_t b[2], const float c[4]) {
    asm volatile(
        "mma.sync.aligned.m16n8k8.row.col.f32.tf32.tf32.f32 "
        "{%0,%1,%2,%3}, {%4,%5,%6,%7}, {%8,%9}, {%10,%11,%12,%13};\n"
        : "=f"(d[0]), "=f"(d[1]), "=f"(d[2]), "=f"(d[3])
        : "r"(a[0]), "r"(a[1]), "r"(a[2]), "r"(a[3]),
          "r"(b[0]), "r"(b[1]),
          "f"(c[0]), "f"(c[1]), "f"(c[2]), "f"(c[3]));
}

// ============================================================================
// Kernel 0: build fp16 B-fragment images (W1/W2/W3) + tf32 U-fragment images.
// ============================================================================
__global__ void prep_kernel(const float* __restrict__ W1, const float* __restrict__ W2,
                            const float* __restrict__ W3, const float* __restrict__ U) {
    __half* gh = (__half*)g_wfrag;
    int idx = blockIdx.x * 256 + threadIdx.x;
    if (idx < 65536) {                    // W2 [256k x 256n]
        int k = idx >> 8, n = idx & 255;
        int chunk = k >> 5, ks = (k >> 4) & 1, kl = k & 15;
        int b_idx = kl >> 3, q = (kl & 7) >> 1, par = kl & 1;
        int wn = n >> 5, nt = (n >> 3) & 3, g = n & 7;
        int slot = chunk * 2048 + ((ks * 8 + wn) * 4 + nt) * 32 + g * 4 + q;
        gh[slot * 4 + b_idx * 2 + par] = __float2half_rn(W2[idx]);
    } else if (idx < 69632) {             // W1 [16k x 256n]
        int t = idx - 65536;
        int k = t >> 8, n = t & 255;
        int b_idx = k >> 3, q = (k & 7) >> 1, par = k & 1;
        int wn = n >> 5, nt = (n >> 3) & 3, g = n & 7;
        int slot = (wn * 4 + nt) * 32 + g * 4 + q;
        gh[65536 + slot * 4 + b_idx * 2 + par] = __float2half_rn(W1[t]);
    } else if (idx < 73728) {             // W3 [256k x 16n]
        int t = idx - 69632;
        int k = t >> 4, n = t & 15;
        int ks = k >> 4, kl = k & 15;
        int b_idx = kl >> 3, q = (kl & 7) >> 1, par = kl & 1;
        int nt = n >> 3, g = n & 7;
        int slot = (ks * 2 + nt) * 32 + g * 4 + q;
        gh[69632 + slot * 4 + b_idx * 2 + par] = __float2half_rn(W3[t]);
    } else if (idx < 74752) {             // ufA: 1024 float2 (z@U B-frags, k=128,n=16)
        int t = idx - 73728;
        int lane = t & 31, nt = (t >> 5) & 1, kk = t >> 6;
        int g = lane >> 2, q = lane & 3;
        g_ufA[t * 2]     = nan0(U[(kk * 8 + q) * RR + nt * 8 + g]);
        g_ufA[t * 2 + 1] = nan0(U[(kk * 8 + q + 4) * RR + nt * 8 + g]);
    } else if (idx < 75776) {             // ufB: 1024 float2 (cs@Ut B-frags, k=16,n=128)
        int t = idx - 74752;
        int lane = t & 31, nt = (t >> 5) & 15, ks = t >> 9;
        int g = lane >> 2, q = lane & 3;
        g_ufB[t * 2]     = nan0(U[(nt * 8 + g) * RR + ks * 8 + q]);
        g_ufB[t * 2 + 1] = nan0(U[(nt * 8 + g) * RR + ks * 8 + q + 4]);
    }
}

// ============================================================================
// Kernel 1: fused MLP, fp16 mma, 64 rows/CTA, 512 threads, 2 CTAs/SM.
// 3-slot W2 ring, 2 chunks always in flight.
// ============================================================================
__global__ void __launch_bounds__(512, 2) mlp_kernel(
    const float* __restrict__ pt, const float* __restrict__ dt_norm_g,
    const float* __restrict__ U,
    const float* __restrict__ b1, const float* __restrict__ b2,
    const float* __restrict__ b3) {
    extern __shared__ char smc[];
    __shared__ float b1s[256], b2s[256], b3s[16], cn2s[16];

    const int tid = threadIdx.x;
    const int wid = tid >> 5, lane = tid & 31;
    const int g = lane >> 2, q = lane & 3;
    const int r0 = blockIdx.x * MTILE;
    const uint32_t sb = smem_u32(smc);
    const char* gw = (const char*)g_wfrag;

    // group 0: W1 frags (8KB) + W3 frags (8KB)
    cpa16(sb + OFF_W1F + tid * 16, gw + 131072 + tid * 16);
    cpa16(sb + OFF_W3F + tid * 16, gw + 139264 + tid * 16);
    cpcommit();
    // groups 1,2: W2 chunks 0,1
#pragma unroll
    for (int c = 0; c < 2; c++) {
#pragma unroll
        for (int i = 0; i < 2; i++) {
            int idx = tid + i * 512;
            cpa16(sb + OFF_RING + c * 16384 + idx * 16, gw + (size_t)c * 16384 + idx * 16);
        }
        cpcommit();
    }

    // --- stage x as fp16 A-frags (nan0) ---
    __half* xf = (__half*)(smc + OFF_XF);
#pragma unroll
    for (int i = 0; i < 2; i++) {
        int idx = tid + i * 512;                 // 1024 elements
        int r = idx >> 4, c = idx & 15;
        float v = nan0(pt[(size_t)(r0 + r) * GD + c]);
        int rr = r & 15, rb = r >> 4;
        int gg = rr & 7, hi8 = rr >> 3;
        int qq = (c & 7) >> 1, par = c & 1;
        int a_idx = ((c >= 8) ? 2 : 0) + hi8;
        int ln = gg * 4 + qq;
        xf[(rb * 32 + ln) * 8 + a_idx * 2 + par] = __float2half_rn(v);
    }
    if (tid < 256) {
        b1s[tid] = b1[tid];
        b2s[tid] = b2[tid];
    }
    if (tid < 16) {
        b3s[tid] = b3[tid];
        float s = 0.f;
        for (int j = 0; j < ZD; j++) {
            float u = nan0(U[j * RR + tid]);
            s += u * u;
        }
        cn2s[tid] = s;
    }
    cpwait<2>();     // W1/W3 ready; chunks 0,1 in flight
    __syncthreads();

    const int wm = wid >> 3, wn = wid & 7;   // 2 x 8 warps

    // ================= GEMM1: h1 = silu(x @ W1 + b1) -> h1 A-frags =========
#pragma unroll
    for (int mt = 0; mt < 2; mt++) {
        int rb = wm * 2 + mt;
        uint4 Av = *(const uint4*)(smc + OFF_XF + (rb * 32 + lane) * 16);
        uint32_t A[4] = {Av.x, Av.y, Av.z, Av.w};
#pragma unroll
        for (int nt = 0; nt < 4; nt++) {
            float acc[4] = {0.f, 0.f, 0.f, 0.f};
            uint2 Bv = *(const uint2*)(smc + OFF_W1F + ((wn * 4 + nt) * 32 + lane) * 8);
            uint32_t B[2] = {Bv.x, Bv.y};
            mma16(acc, A, B, acc);
            int ntile = wn * 4 + nt, cb = ntile * 8;
            float s0 = silu_f(acc[0] + b1s[cb + 2 * q]);
            float s1 = silu_f(acc[1] + b1s[cb + 2 * q + 1]);
            float s2 = silu_f(acc[2] + b1s[cb + 2 * q]);
            float s3 = silu_f(acc[3] + b1s[cb + 2 * q + 1]);
            int kk = ntile >> 1, half = ntile & 1;
            uint2 pk = make_uint2(packh(s0, s1), packh(s2, s3));
            *(uint2*)(smc + OFF_H1F + ((rb * 16 + kk) * 32 + lane) * 16 + half * 8) = pk;
        }
    }
    __syncthreads();

    // ================= GEMM2: h2 = silu(h1 @ W2 + b2), 8 chunks K=32 =======
    float acc[2][4][4];
#pragma unroll
    for (int mt = 0; mt < 2; mt++)
#pragma unroll
        for (int nt = 0; nt < 4; nt++)
#pragma unroll
            for (int i = 0; i < 4; i++) acc[mt][nt][i] = 0.f;

    for (int c = 0; c < 8; c++) {
        if (c == 7) cpwait<0>(); else cpwait<1>();   // chunk c landed, c+1 flying
        __syncthreads();
        if (c + 2 < 8) {   // prefetch c+2 into slot (c+2)%3 == (c-1)%3 (safe post-barrier)
            int j = c + 2;
            int slot = j - (j / 3) * 3;
#pragma unroll
            for (int i = 0; i < 2; i++) {
                int idx = tid + i * 512;
                cpa16(sb + OFF_RING + slot * 16384 + idx * 16,
                      gw + (size_t)j * 16384 + idx * 16);
            }
            cpcommit();
        }
        const char* wb = smc + OFF_RING + (c - (c / 3) * 3) * 16384;
#pragma unroll
        for (int ks = 0; ks < 2; ks++) {
            int kk = c * 2 + ks;
            uint4 A0v = *(const uint4*)(smc + OFF_H1F + (((wm * 2 + 0) * 16 + kk) * 32 + lane) * 16);
            uint4 A1v = *(const uint4*)(smc + OFF_H1F + (((wm * 2 + 1) * 16 + kk) * 32 + lane) * 16);
            uint32_t A0[4] = {A0v.x, A0v.y, A0v.z, A0v.w};
            uint32_t A1[4] = {A1v.x, A1v.y, A1v.z, A1v.w};
#pragma unroll
            for (int nt = 0; nt < 4; nt++) {
                uint2 Bv = *(const uint2*)(wb + (((ks * 8 + wn) * 4 + nt) * 32 + lane) * 8);
                uint32_t B[2] = {Bv.x, Bv.y};
                mma16(acc[0][nt], A0, B, acc[0][nt]);
                mma16(acc[1][nt], A1, B, acc[1][nt]);
            }
        }
    }
    __syncthreads();   // all h1f reads done before h2 frags overlay it

    // epilogue -> h2 A-frags (overlay OFF_H1F)
#pragma unroll
    for (int mt = 0; mt < 2; mt++) {
        int rb = wm * 2 + mt;
#pragma unroll
        for (int nt = 0; nt < 4; nt++) {
            int ntile = wn * 4 + nt, cb = ntile * 8;
            float s0 = silu_f(acc[mt][nt][0] + b2s[cb + 2 * q]);
            float s1 = silu_f(acc[mt][nt][1] + b2s[cb + 2 * q + 1]);
            float s2 = silu_f(acc[mt][nt][2] + b2s[cb + 2 * q]);
            float s3 = silu_f(acc[mt][nt][3] + b2s[cb + 2 * q + 1]);
            int kk = ntile >> 1, half = ntile & 1;
            uint2 pk = make_uint2(packh(s0, s1), packh(s2, s3));
            *(uint2*)(smc + OFF_H1F + ((rb * 16 + kk) * 32 + lane) * 16 + half * 8) = pk;
        }
    }
    __syncthreads();

    // ================= GEMM3: h = h2 @ W3 (4-way K-split over warps) =======
    float* hp = (float*)(smc + OFF_RING);   // [4][64][20] fp32 partials
    {
        int rb = wid & 3, wk = wid >> 2;
        float a3[2][4] = {{0.f, 0.f, 0.f, 0.f}, {0.f, 0.f, 0.f, 0.f}};
#pragma unroll
        for (int ksl = 0; ksl < 4; ksl++) {
            int kk = wk * 4 + ksl;
            uint4 Av = *(const uint4*)(smc + OFF_H1F + ((rb * 16 + kk) * 32 + lane) * 16);
            uint32_t A[4] = {Av.x, Av.y, Av.z, Av.w};
#pragma unroll
            for (int nt = 0; nt < 2; nt++) {
                uint2 Bv = *(const uint2*)(smc + OFF_W3F + ((kk * 2 + nt) * 32 + lane) * 8);
                uint32_t B[2] = {Bv.x, Bv.y};
                mma16(a3[nt], A, B, a3[nt]);
            }
        }
#pragma unroll
        for (int nt = 0; nt < 2; nt++) {
            int c0 = nt * 8 + 2 * q;
            *(float2*)&hp[(wk * 64 + rb * 16 + g) * 20 + c0]     = make_float2(a3[nt][0], a3[nt][1]);
            *(float2*)&hp[(wk * 64 + rb * 16 + g + 8) * 20 + c0] = make_float2(a3[nt][2], a3[nt][3]);
        }
    }
    __syncthreads();

    // ================= per-row epilogue =================
    if (tid < 64) {
        int row = tid;
        float s[16], fro2 = 0.f;
#pragma unroll
        for (int r = 0; r < 16; r++) {
            float v = b3s[r];
#pragma unroll
            for (int p = 0; p < 4; p++) v += hp[(p * 64 + row) * 20 + r];
            float sr = 2.f / (1.f + __expf(-v));
            s[r] = sr;
            fro2 += sr * sr * cn2s[r];
        }
        float fro = sqrtf(fro2);
        float scale = fminf(2.2627416997969522f / fmaxf(fro, 1e-9f), 1.f);

        float v = dt_norm_g[r0 + row];
        if (isnan(v)) v = 0.f;
        v = fminf(fmaxf(v, 0.f), 1.f);
        float logdt = fminf(-3.f + v * 11.f, 2.7781512503836436f);   // log10(600)
        float dt = fmaxf(expf(logdt * 2.302585092994046f), 1e-30f);
        float lamg = expf(-0.1f * dt);
        g_lamg[r0 + row] = lamg;
#pragma unroll
        for (int r = 0; r < 16; r++) {
            float ss = s[r] * scale;
            float lp = expf(-ss * ss * dt) * lamg;
            g_d[(size_t)(r0 + row) * 16 + r] = lp - lamg;
        }
    }
}

// ============================================================================
// Kernel 2: z_next = lam_g*z + ((lam_para - lam_g) .* (z@U)) @ U^T
// U B-frags prebuilt by prep; 4 CTAs/SM.
// ============================================================================
__global__ void __launch_bounds__(256, 4) dyn_kernel(
    const float* __restrict__ z, float* __restrict__ out) {
    extern __shared__ float sm2[];
    float* zs  = sm2 + DOFF_ZS;
    float* cs  = sm2 + DOFF_CS;
    float* lg  = sm2 + DOFF_LG;
    const char* ufA = (const char*)(sm2 + DOFF_UFA);
    const char* ufB = (const char*)(sm2 + DOFF_UFB);
    const int tid = threadIdx.x;
    const int wid = tid >> 5, lane = tid & 31;
    const int g = lane >> 2, q = lane & 3;
    const int r0 = blockIdx.x * MTILE;
    const uint32_t sb = smem_u32(sm2);

    // --- cp.async: U frag images (16KB) ---
#pragma unroll
    for (int i = 0; i < 2; i++) {
        int idx = tid + i * 256;                 // 512 x 16B = 8KB
        cpa16(sb + DOFF_UFA * 4 + idx * 16, (const char*)g_ufA + idx * 16);
        cpa16(sb + DOFF_UFB * 4 + idx * 16, (const char*)g_ufB + idx * 16);
    }
    cpcommit();

    // --- stage z (nan0, float4) ---
#pragma unroll
    for (int i = 0; i < 8; i++) {
        int idx = tid + i * 256;
        int row = idx >> 5, c4 = (idx & 31) << 2;
        float4 v = *reinterpret_cast<const float4*>(&z[(size_t)(r0 + row) * ZD + c4]);
        v.x = nan0(v.x); v.y = nan0(v.y); v.z = nan0(v.z); v.w = nan0(v.w);
        *reinterpret_cast<float4*>(&zs[row * 132 + c4]) = v;
    }
    if (tid < 64) lg[tid] = g_lamg[r0 + tid];
    cpwait<0>();
    __syncthreads();

    // ===== GEMM A: cs[row][r] = d[row][r] * (z @ U)[row][r] =====
    {
        int mt = wid >> 1, nt = wid & 1;
        int rbase = mt * 16, cbase = nt * 8;
        float acc[4] = {0.f, 0.f, 0.f, 0.f};
#pragma unroll
        for (int kk = 0; kk < 16; kk++) {
            int k0 = kk * 8;
            uint32_t a[4] = {
                fbits(zs[(rbase + g) * 132 + k0 + q]),
                fbits(zs[(rbase + g + 8) * 132 + k0 + q]),
                fbits(zs[(rbase + g) * 132 + k0 + q + 4]),
                fbits(zs[(rbase + g + 8) * 132 + k0 + q + 4])};
            uint2 bv = *(const uint2*)(ufA + ((kk * 2 + nt) * 32 + lane) * 8);
            uint32_t b[2] = {bv.x, bv.y};
            mma8(acc, a, b, acc);
        }
        int row0 = rbase + g, row1 = rbase + g + 8;
        int c0 = cbase + 2 * q, c1 = c0 + 1;
        cs[row0 * 20 + c0] = acc[0] * g_d[(size_t)(r0 + row0) * 16 + c0];
        cs[row0 * 20 + c1] = acc[1] * g_d[(size_t)(r0 + row0) * 16 + c1];
        cs[row1 * 20 + c0] = acc[2] * g_d[(size_t)(r0 + row1) * 16 + c0];
        cs[row1 * 20 + c1] = acc[3] * g_d[(size_t)(r0 + row1) * 16 + c1];
    }
    __syncthreads();

    // ===== GEMM B + identity, direct to global =====
    {
        int wm = wid >> 1, wn = wid & 1;
        int rbase = wm * 16;
        float acc[8][4];
#pragma unroll
        for (int nt = 0; nt < 8; nt++)
#pragma unroll
            for (int i = 0; i < 4; i++) acc[nt][i] = 0.f;
#pragma unroll
        for (int ks = 0; ks < 2; ks++) {
            int k0 = ks * 8;
            uint32_t a[4] = {
                fbits(cs[(rbase + g) * 20 + k0 + q]),
                fbits(cs[(rbase + g + 8) * 20 + k0 + q]),
                fbits(cs[(rbase + g) * 20 + k0 + q + 4]),
                fbits(cs[(rbase + g + 8) * 20 + k0 + q + 4])};
#pragma unroll
            for (int nt = 0; nt < 8; nt++) {
                uint2 bv = *(const uint2*)(ufB + ((ks * 16 + wn * 8 + nt) * 32 + lane) * 8);
                uint32_t b[2] = {bv.x, bv.y};
                mma8(acc[nt], a, b, acc[nt]);
            }
        }
        int row0 = rbase + g, row1 = rbase + g + 8;
        float l0 = lg[row0], l1 = lg[row1];
        size_t gr0 = (size_t)(r0 + row0) * ZD, gr1 = (size_t)(r0 + row1) * ZD;
#pragma unroll
        for (int nt = 0; nt < 8; nt++) {
            int cb = (wn * 8 + nt) * 8;
            int c0 = cb + 2 * q;
            float2 z0 = *reinterpret_cast<const float2*>(&zs[row0 * 132 + c0]);
            float2 o0;
            o0.x = l0 * z0.x + acc[nt][0];
            o0.y = l0 * z0.y + acc[nt][1];
            *reinterpret_cast<float2*>(&out[gr0 + c0]) = o0;
            float2 z1 = *reinterpret_cast<const float2*>(&zs[row1 * 132 + c0]);
            float2 o1;
            o1.x = l1 * z1.x + acc[nt][2];
            o1.y = l1 * z1.y + acc[nt][3];
            *reinterpret_cast<float2*>(&out[gr1 + c0]) = o1;
        }
    }
}

extern "C" void kernel_launch(void* const* d_in, const int* in_sizes, int n_in,
                              void* d_out, int out_size) {
    const float* pt      = (const float*)d_in[0];
    const float* z       = (const float*)d_in[1];
    const float* dt_norm = (const float*)d_in[2];
    const float* base_U  = (const float*)d_in[3];
    const float* W1      = (const float*)d_in[4];
    const float* b1      = (const float*)d_in[5];
    const float* W2      = (const float*)d_in[6];
    const float* b2      = (const float*)d_in[7];
    const float* W3      = (const float*)d_in[8];
    const float* b3      = (const float*)d_in[9];
    float* out = (float*)d_out;

    cudaFuncSetAttribute(mlp_kernel, cudaFuncAttributeMaxDynamicSharedMemorySize, SMEM_BYTES);
    cudaFuncSetAttribute(dyn_kernel, cudaFuncAttributeMaxDynamicSharedMemorySize,
                         DYN_SMEM_FLOATS * 4);

    prep_kernel<<<296, 256>>>(W1, W2, W3, base_U);
    mlp_kernel<<<NBLK, 512, SMEM_BYTES>>>(pt, dt_norm, base_U, b1, b2, b3);
    dyn_kernel<<<NBLK, 256, DYN_SMEM_FLOATS * 4>>>(z, out);
}

// round 9
// speedup vs baseline: 1.2242x; 1.2242x over previous
#include <cuda_runtime.h>
#include <cuda_fp16.h>
#include <cstdint>
#include <math.h>

#define BATCH 262144
#define GD 16
#define HID 256
#define RR 16
#define ZD 128
#define MTILE 64
#define NBLK (BATCH / MTILE)

// ---- mlp dynamic smem layout (bytes) ----
#define OFF_XF   0        // x A-frags: 4rb x 32lane x 16B = 2048
#define OFF_W1F  2048     // W1 B-frags: 1024 slots x 8B = 8192
#define OFF_W3F  10240    // W3 B-frags: 1024 slots x 8B = 8192
#define OFF_H1F  18432    // h1 A-frags 32768 (h2 frags overlay after GEMM2)
#define OFF_RING 51200    // W2 ring 3 x 16384 = 49152 (GEMM3 partials overlay)
#define SMEM_BYTES 100352

// ---- dyn dynamic smem layout (floats) ----
#define DOFF_ZS  0        // 64*132 = 8448
#define DOFF_CS  8448     // 64*20  = 1280
#define DOFF_LG  9728     // 64
#define DOFF_UFA 9792     // 2048 (16kk x 2nt x 32lane float2)
#define DOFF_UFB 11840    // 2048 (2ks x 16nt x 32lane float2)
#define DYN_SMEM_FLOATS 13888   // 55552 bytes

// scratch (device globals: allocation-free)
__device__ float g_lamg[BATCH];
__device__ float g_d[BATCH * RR];
// fp16 fragment images: W2 8 chunks x 16KB @u32 0, W1 @u32 32768, W3 @u32 34816
__device__ __align__(256) uint32_t g_wfrag[36864];
// tf32 U fragment images (fp32): ufA 2048 f, ufB 2048 f
__device__ __align__(256) float g_ufA[2048];
__device__ __align__(256) float g_ufB[2048];

__device__ __forceinline__ uint32_t fbits(float x) { return __float_as_uint(x); }
__device__ __forceinline__ float nan0(float v) { return isfinite(v) ? v : 0.f; }
__device__ __forceinline__ float silu_f(float x) { return x * (1.f / (1.f + __expf(-x))); }
__device__ __forceinline__ uint32_t packh(float lo, float hi) {
    uint32_t u;
    asm("cvt.rn.f16x2.f32 %0, %1, %2;" : "=r"(u) : "f"(hi), "f"(lo));
    return u;
}
// silu on a pair via ONE MUFU: silu(x) = (x/2) * (1 + tanh(x/2)); result f16x2
__device__ __forceinline__ uint32_t silu2h(float x0, float x1) {
    uint32_t hx = packh(0.5f * x0, 0.5f * x1);
    uint32_t t, opt, r;
    asm("tanh.approx.f16x2 %0, %1;" : "=r"(t) : "r"(hx));
    asm("add.f16x2 %0, %1, %2;" : "=r"(opt) : "r"(t), "r"(0x3C003C00u));  // 1+t
    asm("mul.f16x2 %0, %1, %2;" : "=r"(r) : "r"(hx), "r"(opt));
    return r;
}
__device__ __forceinline__ uint32_t smem_u32(const void* p) {
    uint32_t a;
    asm("{ .reg .u64 t; cvta.to.shared.u64 t, %1; cvt.u32.u64 %0, t; }" : "=r"(a) : "l"(p));
    return a;
}
__device__ __forceinline__ void cpa16(uint32_t saddr, const void* g) {
    asm volatile("cp.async.cg.shared.global [%0], [%1], 16;\n" ::"r"(saddr), "l"(g));
}
__device__ __forceinline__ void cpcommit() { asm volatile("cp.async.commit_group;\n"); }
template <int N>
__device__ __forceinline__ void cpwait() { asm volatile("cp.async.wait_group %0;\n" ::"n"(N)); }

// fp16 mma m16n8k16, fp32 accumulate
__device__ __forceinline__ void mma16(float d[4], const uint32_t a[4],
                                      const uint32_t b[2], const float c[4]) {
    asm volatile(
        "mma.sync.aligned.m16n8k16.row.col.f32.f16.f16.f32 "
        "{%0,%1,%2,%3}, {%4,%5,%6,%7}, {%8,%9}, {%10,%11,%12,%13};\n"
        : "=f"(d[0]), "=f"(d[1]), "=f"(d[2]), "=f"(d[3])
        : "r"(a[0]), "r"(a[1]), "r"(a[2]), "r"(a[3]),
          "r"(b[0]), "r"(b[1]),
          "f"(c[0]), "f"(c[1]), "f"(c[2]), "f"(c[3]));
}
// tf32 mma m16n8k8 (dyn kernel)
__device__ __forceinline__ void mma8(float d[4], const uint32_t a[4],
                                     const uint32_t b[2], const float c[4]) {
    asm volatile(
        "mma.sync.aligned.m16n8k8.row.col.f32.tf32.tf32.f32 "
        "{%0,%1,%2,%3}, {%4,%5,%6,%7}, {%8,%9}, {%10,%11,%12,%13};\n"
        : "=f"(d[0]), "=f"(d[1]), "=f"(d[2]), "=f"(d[3])
        : "r"(a[0]), "r"(a[1]), "r"(a[2]), "r"(a[3]),
          "r"(b[0]), "r"(b[1]),
          "f"(c[0]), "f"(c[1]), "f"(c[2]), "f"(c[3]));
}

// ============================================================================
// Kernel 0: build fp16 B-fragment images (W1/W2/W3) + tf32 U-fragment images.
// ============================================================================
__global__ void prep_kernel(const float* __restrict__ W1, const float* __restrict__ W2,
                            const float* __restrict__ W3, const float* __restrict__ U) {
    __half* gh = (__half*)g_wfrag;
    int idx = blockIdx.x * 256 + threadIdx.x;
    if (idx < 65536) {                    // W2 [256k x 256n]
        int k = idx >> 8, n = idx & 255;
        int chunk = k >> 5, ks = (k >> 4) & 1, kl = k & 15;
        int b_idx = kl >> 3, q = (kl & 7) >> 1, par = kl & 1;
        int wn = n >> 5, nt = (n >> 3) & 3, g = n & 7;
        int slot = chunk * 2048 + ((ks * 8 + wn) * 4 + nt) * 32 + g * 4 + q;
        gh[slot * 4 + b_idx * 2 + par] = __float2half_rn(W2[idx]);
    } else if (idx < 69632) {             // W1 [16k x 256n]
        int t = idx - 65536;
        int k = t >> 8, n = t & 255;
        int b_idx = k >> 3, q = (k & 7) >> 1, par = k & 1;
        int wn = n >> 5, nt = (n >> 3) & 3, g = n & 7;
        int slot = (wn * 4 + nt) * 32 + g * 4 + q;
        gh[65536 + slot * 4 + b_idx * 2 + par] = __float2half_rn(W1[t]);
    } else if (idx < 73728) {             // W3 [256k x 16n]
        int t = idx - 69632;
        int k = t >> 4, n = t & 15;
        int ks = k >> 4, kl = k & 15;
        int b_idx = kl >> 3, q = (kl & 7) >> 1, par = kl & 1;
        int nt = n >> 3, g = n & 7;
        int slot = (ks * 2 + nt) * 32 + g * 4 + q;
        gh[69632 + slot * 4 + b_idx * 2 + par] = __float2half_rn(W3[t]);
    } else if (idx < 74752) {             // ufA: 1024 float2 (z@U B-frags, k=128,n=16)
        int t = idx - 73728;
        int lane = t & 31, nt = (t >> 5) & 1, kk = t >> 6;
        int g = lane >> 2, q = lane & 3;
        g_ufA[t * 2]     = nan0(U[(kk * 8 + q) * RR + nt * 8 + g]);
        g_ufA[t * 2 + 1] = nan0(U[(kk * 8 + q + 4) * RR + nt * 8 + g]);
    } else if (idx < 75776) {             // ufB: 1024 float2 (cs@Ut B-frags, k=16,n=128)
        int t = idx - 74752;
        int lane = t & 31, nt = (t >> 5) & 15, ks = t >> 9;
        int g = lane >> 2, q = lane & 3;
        g_ufB[t * 2]     = nan0(U[(nt * 8 + g) * RR + ks * 8 + q]);
        g_ufB[t * 2 + 1] = nan0(U[(nt * 8 + g) * RR + ks * 8 + q + 4]);
    }
}

// ============================================================================
// Kernel 1: fused MLP, fp16 mma, 64 rows/CTA, 512 threads, 2 CTAs/SM.
// 3-slot W2 ring (2 chunks in flight); tanh.approx.f16x2 silu epilogues.
// ============================================================================
__global__ void __launch_bounds__(512, 2) mlp_kernel(
    const float* __restrict__ pt, const float* __restrict__ dt_norm_g,
    const float* __restrict__ U,
    const float* __restrict__ b1, const float* __restrict__ b2,
    const float* __restrict__ b3) {
    extern __shared__ char smc[];
    __shared__ float b1s[256], b2s[256], b3s[16], cn2s[16];

    const int tid = threadIdx.x;
    const int wid = tid >> 5, lane = tid & 31;
    const int g = lane >> 2, q = lane & 3;
    const int r0 = blockIdx.x * MTILE;
    const uint32_t sb = smem_u32(smc);
    const char* gw = (const char*)g_wfrag;

    // group 0: W1 frags (8KB) + W3 frags (8KB)
    cpa16(sb + OFF_W1F + tid * 16, gw + 131072 + tid * 16);
    cpa16(sb + OFF_W3F + tid * 16, gw + 139264 + tid * 16);
    cpcommit();
    // groups 1,2: W2 chunks 0,1
#pragma unroll
    for (int c = 0; c < 2; c++) {
#pragma unroll
        for (int i = 0; i < 2; i++) {
            int idx = tid + i * 512;
            cpa16(sb + OFF_RING + c * 16384 + idx * 16, gw + (size_t)c * 16384 + idx * 16);
        }
        cpcommit();
    }

    // --- stage x as fp16 A-frags (nan0) ---
    __half* xf = (__half*)(smc + OFF_XF);
#pragma unroll
    for (int i = 0; i < 2; i++) {
        int idx = tid + i * 512;                 // 1024 elements
        int r = idx >> 4, c = idx & 15;
        float v = nan0(pt[(size_t)(r0 + r) * GD + c]);
        int rr = r & 15, rb = r >> 4;
        int gg = rr & 7, hi8 = rr >> 3;
        int qq = (c & 7) >> 1, par = c & 1;
        int a_idx = ((c >= 8) ? 2 : 0) + hi8;
        int ln = gg * 4 + qq;
        xf[(rb * 32 + ln) * 8 + a_idx * 2 + par] = __float2half_rn(v);
    }
    if (tid < 256) {
        b1s[tid] = b1[tid];
        b2s[tid] = b2[tid];
    }
    if (tid < 16) {
        b3s[tid] = b3[tid];
        float s = 0.f;
        for (int j = 0; j < ZD; j++) {
            float u = nan0(U[j * RR + tid]);
            s += u * u;
        }
        cn2s[tid] = s;
    }
    cpwait<2>();     // W1/W3 ready; chunks 0,1 in flight
    __syncthreads();

    const int wm = wid >> 3, wn = wid & 7;   // 2 x 8 warps

    // ================= GEMM1: h1 = silu(x @ W1 + b1) -> h1 A-frags =========
#pragma unroll
    for (int mt = 0; mt < 2; mt++) {
        int rb = wm * 2 + mt;
        uint4 Av = *(const uint4*)(smc + OFF_XF + (rb * 32 + lane) * 16);
        uint32_t A[4] = {Av.x, Av.y, Av.z, Av.w};
#pragma unroll
        for (int nt = 0; nt < 4; nt++) {
            float acc[4] = {0.f, 0.f, 0.f, 0.f};
            uint2 Bv = *(const uint2*)(smc + OFF_W1F + ((wn * 4 + nt) * 32 + lane) * 8);
            uint32_t B[2] = {Bv.x, Bv.y};
            mma16(acc, A, B, acc);
            int ntile = wn * 4 + nt, cb = ntile * 8;
            float bx = b1s[cb + 2 * q], by = b1s[cb + 2 * q + 1];
            int kk = ntile >> 1, half = ntile & 1;
            uint2 pk = make_uint2(silu2h(acc[0] + bx, acc[1] + by),
                                  silu2h(acc[2] + bx, acc[3] + by));
            *(uint2*)(smc + OFF_H1F + ((rb * 16 + kk) * 32 + lane) * 16 + half * 8) = pk;
        }
    }
    __syncthreads();

    // ================= GEMM2: h2 = silu(h1 @ W2 + b2), 8 chunks K=32 =======
    float acc[2][4][4];
#pragma unroll
    for (int mt = 0; mt < 2; mt++)
#pragma unroll
        for (int nt = 0; nt < 4; nt++)
#pragma unroll
            for (int i = 0; i < 4; i++) acc[mt][nt][i] = 0.f;

    for (int c = 0; c < 8; c++) {
        if (c == 7) cpwait<0>(); else cpwait<1>();   // chunk c landed, c+1 flying
        __syncthreads();
        if (c + 2 < 8) {   // prefetch c+2 into slot (c+2)%3 == (c-1)%3 (safe post-barrier)
            int j = c + 2;
            int slot = j - (j / 3) * 3;
#pragma unroll
            for (int i = 0; i < 2; i++) {
                int idx = tid + i * 512;
                cpa16(sb + OFF_RING + slot * 16384 + idx * 16,
                      gw + (size_t)j * 16384 + idx * 16);
            }
            cpcommit();
        }
        const char* wb = smc + OFF_RING + (c - (c / 3) * 3) * 16384;
#pragma unroll
        for (int ks = 0; ks < 2; ks++) {
            int kk = c * 2 + ks;
            uint4 A0v = *(const uint4*)(smc + OFF_H1F + (((wm * 2 + 0) * 16 + kk) * 32 + lane) * 16);
            uint4 A1v = *(const uint4*)(smc + OFF_H1F + (((wm * 2 + 1) * 16 + kk) * 32 + lane) * 16);
            uint32_t A0[4] = {A0v.x, A0v.y, A0v.z, A0v.w};
            uint32_t A1[4] = {A1v.x, A1v.y, A1v.z, A1v.w};
#pragma unroll
            for (int nt = 0; nt < 4; nt++) {
                uint2 Bv = *(const uint2*)(wb + (((ks * 8 + wn) * 4 + nt) * 32 + lane) * 8);
                uint32_t B[2] = {Bv.x, Bv.y};
                mma16(acc[0][nt], A0, B, acc[0][nt]);
                mma16(acc[1][nt], A1, B, acc[1][nt]);
            }
        }
    }
    __syncthreads();   // all h1f reads done before h2 frags overlay it

    // epilogue -> h2 A-frags (overlay OFF_H1F)
#pragma unroll
    for (int mt = 0; mt < 2; mt++) {
        int rb = wm * 2 + mt;
#pragma unroll
        for (int nt = 0; nt < 4; nt++) {
            int ntile = wn * 4 + nt, cb = ntile * 8;
            float bx = b2s[cb + 2 * q], by = b2s[cb + 2 * q + 1];
            int kk = ntile >> 1, half = ntile & 1;
            uint2 pk = make_uint2(silu2h(acc[mt][nt][0] + bx, acc[mt][nt][1] + by),
                                  silu2h(acc[mt][nt][2] + bx, acc[mt][nt][3] + by));
            *(uint2*)(smc + OFF_H1F + ((rb * 16 + kk) * 32 + lane) * 16 + half * 8) = pk;
        }
    }
    __syncthreads();

    // ================= GEMM3: h = h2 @ W3 (4-way K-split over warps) =======
    float* hp = (float*)(smc + OFF_RING);   // [4][64][20] fp32 partials
    {
        int rb = wid & 3, wk = wid >> 2;
        float a3[2][4] = {{0.f, 0.f, 0.f, 0.f}, {0.f, 0.f, 0.f, 0.f}};
#pragma unroll
        for (int ksl = 0; ksl < 4; ksl++) {
            int kk = wk * 4 + ksl;
            uint4 Av = *(const uint4*)(smc + OFF_H1F + ((rb * 16 + kk) * 32 + lane) * 16);
            uint32_t A[4] = {Av.x, Av.y, Av.z, Av.w};
#pragma unroll
            for (int nt = 0; nt < 2; nt++) {
                uint2 Bv = *(const uint2*)(smc + OFF_W3F + ((kk * 2 + nt) * 32 + lane) * 8);
                uint32_t B[2] = {Bv.x, Bv.y};
                mma16(a3[nt], A, B, a3[nt]);
            }
        }
#pragma unroll
        for (int nt = 0; nt < 2; nt++) {
            int c0 = nt * 8 + 2 * q;
            *(float2*)&hp[(wk * 64 + rb * 16 + g) * 20 + c0]     = make_float2(a3[nt][0], a3[nt][1]);
            *(float2*)&hp[(wk * 64 + rb * 16 + g + 8) * 20 + c0] = make_float2(a3[nt][2], a3[nt][3]);
        }
    }
    __syncthreads();

    // ================= per-row epilogue (exact fp32 path) =================
    if (tid < 64) {
        int row = tid;
        float s[16], fro2 = 0.f;
#pragma unroll
        for (int r = 0; r < 16; r++) {
            float v = b3s[r];
#pragma unroll
            for (int p = 0; p < 4; p++) v += hp[(p * 64 + row) * 20 + r];
            float sr = 2.f / (1.f + __expf(-v));
            s[r] = sr;
            fro2 += sr * sr * cn2s[r];
        }
        float fro = sqrtf(fro2);
        float scale = fminf(2.2627416997969522f / fmaxf(fro, 1e-9f), 1.f);

        float v = dt_norm_g[r0 + row];
        if (isnan(v)) v = 0.f;
        v = fminf(fmaxf(v, 0.f), 1.f);
        float logdt = fminf(-3.f + v * 11.f, 2.7781512503836436f);   // log10(600)
        float dt = fmaxf(expf(logdt * 2.302585092994046f), 1e-30f);
        float lamg = expf(-0.1f * dt);
        g_lamg[r0 + row] = lamg;
#pragma unroll
        for (int r = 0; r < 16; r++) {
            float ss = s[r] * scale;
            float lp = expf(-ss * ss * dt) * lamg;
            g_d[(size_t)(r0 + row) * 16 + r] = lp - lamg;
        }
    }
}

// ============================================================================
// Kernel 2: z_next = lam_g*z + ((lam_para - lam_g) .* (z@U)) @ U^T
// U B-frags prebuilt by prep; 4 CTAs/SM.
// ============================================================================
__global__ void __launch_bounds__(256, 4) dyn_kernel(
    const float* __restrict__ z, float* __restrict__ out) {
    extern __shared__ float sm2[];
    float* zs  = sm2 + DOFF_ZS;
    float* cs  = sm2 + DOFF_CS;
    float* lg  = sm2 + DOFF_LG;
    const char* ufA = (const char*)(sm2 + DOFF_UFA);
    const char* ufB = (const char*)(sm2 + DOFF_UFB);
    const int tid = threadIdx.x;
    const int wid = tid >> 5, lane = tid & 31;
    const int g = lane >> 2, q = lane & 3;
    const int r0 = blockIdx.x * MTILE;
    const uint32_t sb = smem_u32(sm2);

    // --- cp.async: U frag images (16KB) ---
#pragma unroll
    for (int i = 0; i < 2; i++) {
        int idx = tid + i * 256;                 // 512 x 16B = 8KB
        cpa16(sb + DOFF_UFA * 4 + idx * 16, (const char*)g_ufA + idx * 16);
        cpa16(sb + DOFF_UFB * 4 + idx * 16, (const char*)g_ufB + idx * 16);
    }
    cpcommit();

    // --- stage z (nan0, float4) ---
#pragma unroll
    for (int i = 0; i < 8; i++) {
        int idx = tid + i * 256;
        int row = idx >> 5, c4 = (idx & 31) << 2;
        float4 v = *reinterpret_cast<const float4*>(&z[(size_t)(r0 + row) * ZD + c4]);
        v.x = nan0(v.x); v.y = nan0(v.y); v.z = nan0(v.z); v.w = nan0(v.w);
        *reinterpret_cast<float4*>(&zs[row * 132 + c4]) = v;
    }
    if (tid < 64) lg[tid] = g_lamg[r0 + tid];
    cpwait<0>();
    __syncthreads();

    // ===== GEMM A: cs[row][r] = d[row][r] * (z @ U)[row][r] =====
    {
        int mt = wid >> 1, nt = wid & 1;
        int rbase = mt * 16, cbase = nt * 8;
        float acc[4] = {0.f, 0.f, 0.f, 0.f};
#pragma unroll
        for (int kk = 0; kk < 16; kk++) {
            int k0 = kk * 8;
            uint32_t a[4] = {
                fbits(zs[(rbase + g) * 132 + k0 + q]),
                fbits(zs[(rbase + g + 8) * 132 + k0 + q]),
                fbits(zs[(rbase + g) * 132 + k0 + q + 4]),
                fbits(zs[(rbase + g + 8) * 132 + k0 + q + 4])};
            uint2 bv = *(const uint2*)(ufA + ((kk * 2 + nt) * 32 + lane) * 8);
            uint32_t b[2] = {bv.x, bv.y};
            mma8(acc, a, b, acc);
        }
        int row0 = rbase + g, row1 = rbase + g + 8;
        int c0 = cbase + 2 * q, c1 = c0 + 1;
        cs[row0 * 20 + c0] = acc[0] * g_d[(size_t)(r0 + row0) * 16 + c0];
        cs[row0 * 20 + c1] = acc[1] * g_d[(size_t)(r0 + row0) * 16 + c1];
        cs[row1 * 20 + c0] = acc[2] * g_d[(size_t)(r0 + row1) * 16 + c0];
        cs[row1 * 20 + c1] = acc[3] * g_d[(size_t)(r0 + row1) * 16 + c1];
    }
    __syncthreads();

    // ===== GEMM B + identity, direct to global =====
    {
        int wm = wid >> 1, wn = wid & 1;
        int rbase = wm * 16;
        float acc[8][4];
#pragma unroll
        for (int nt = 0; nt < 8; nt++)
#pragma unroll
            for (int i = 0; i < 4; i++) acc[nt][i] = 0.f;
#pragma unroll
        for (int ks = 0; ks < 2; ks++) {
            int k0 = ks * 8;
            uint32_t a[4] = {
                fbits(cs[(rbase + g) * 20 + k0 + q]),
                fbits(cs[(rbase + g + 8) * 20 + k0 + q]),
                fbits(cs[(rbase + g) * 20 + k0 + q + 4]),
                fbits(cs[(rbase + g + 8) * 20 + k0 + q + 4])};
#pragma unroll
            for (int nt = 0; nt < 8; nt++) {
                uint2 bv = *(const uint2*)(ufB + ((ks * 16 + wn * 8 + nt) * 32 + lane) * 8);
                uint32_t b[2] = {bv.x, bv.y};
                mma8(acc[nt], a, b, acc[nt]);
            }
        }
        int row0 = rbase + g, row1 = rbase + g + 8;
        float l0 = lg[row0], l1 = lg[row1];
        size_t gr0 = (size_t)(r0 + row0) * ZD, gr1 = (size_t)(r0 + row1) * ZD;
#pragma unroll
        for (int nt = 0; nt < 8; nt++) {
            int cb = (wn * 8 + nt) * 8;
            int c0 = cb + 2 * q;
            float2 z0 = *reinterpret_cast<const float2*>(&zs[row0 * 132 + c0]);
            float2 o0;
            o0.x = l0 * z0.x + acc[nt][0];
            o0.y = l0 * z0.y + acc[nt][1];
            *reinterpret_cast<float2*>(&out[gr0 + c0]) = o0;
            float2 z1 = *reinterpret_cast<const float2*>(&zs[row1 * 132 + c0]);
            float2 o1;
            o1.x = l1 * z1.x + acc[nt][2];
            o1.y = l1 * z1.y + acc[nt][3];
            *reinterpret_cast<float2*>(&out[gr1 + c0]) = o1;
        }
    }
}

extern "C" void kernel_launch(void* const* d_in, const int* in_sizes, int n_in,
                              void* d_out, int out_size) {
    const float* pt      = (const float*)d_in[0];
    const float* z       = (const float*)d_in[1];
    const float* dt_norm = (const float*)d_in[2];
    const float* base_U  = (const float*)d_in[3];
    const float* W1      = (const float*)d_in[4];
    const float* b1      = (const float*)d_in[5];
    const float* W2      = (const float*)d_in[6];
    const float* b2      = (const float*)d_in[7];
    const float* W3      = (const float*)d_in[8];
    const float* b3      = (const float*)d_in[9];
    float* out = (float*)d_out;

    cudaFuncSetAttribute(mlp_kernel, cudaFuncAttributeMaxDynamicSharedMemorySize, SMEM_BYTES);
    cudaFuncSetAttribute(dyn_kernel, cudaFuncAttributeMaxDynamicSharedMemorySize,
                         DYN_SMEM_FLOATS * 4);

    prep_kernel<<<296, 256>>>(W1, W2, W3, base_U);
    mlp_kernel<<<NBLK, 512, SMEM_BYTES>>>(pt, dt_norm, base_U, b1, b2, b3);
    dyn_kernel<<<NBLK, 256, DYN_SMEM_FLOATS * 4>>>(z, out);
}

// round 10
// speedup vs baseline: 1.3093x; 1.0695x over previous
#include <cuda_runtime.h>
#include <cuda_fp16.h>
#include <cstdint>
#include <math.h>

#define BATCH 262144
#define GD 16
#define HID 256
#define RR 16
#define ZD 128
#define MTILE 64
#define NBLK (BATCH / MTILE)

// ---- fused kernel dynamic smem layout (bytes) ----
#define OFF_XF   0        // x A-frags 2048        [hp overlays XF+W1F in GEMM3]
#define OFF_W1F  2048     // W1 B-frags 8192
#define OFF_W3F  10240    // W3 B-frags 8192       [ufB overlays after GEMM3]
#define OFF_H1F  18432    // h1/h2 A-frags 32768   [ufA overlays after GEMM3]
#define OFF_RING 51200    // W2 ring 3x16384=49152 [zs/cs/ds/lg overlay after GEMM2]
#define SMEM_BYTES 100352
// overlays
#define OFF_HP   0            // 2*64*20*4 = 10240 (GEMM3 partials)
#define OFF_UFB  10240        // 8192
#define OFF_UFA  18432        // 8192
#define OFF_ZS   51200        // 64*132*4 = 33792
#define OFF_CS   84992        // 64*20*4  = 5120
#define OFF_DS   90112        // 64*20*4  = 5120
#define OFF_LG   95232        // 256

// device-global weight images (allocation-free scratch)
__device__ __align__(256) uint32_t g_wfrag[36864];  // W2 8x16KB, W1 @u32 32768, W3 @u32 34816
__device__ __align__(256) float g_ufA[2048];
__device__ __align__(256) float g_ufB[2048];

__device__ __forceinline__ uint32_t fbits(float x) { return __float_as_uint(x); }
__device__ __forceinline__ float nan0(float v) { return isfinite(v) ? v : 0.f; }
__device__ __forceinline__ uint32_t packh(float lo, float hi) {
    uint32_t u;
    asm("cvt.rn.f16x2.f32 %0, %1, %2;" : "=r"(u) : "f"(hi), "f"(lo));
    return u;
}
// silu pair via ONE MUFU: silu(x) = (x/2)*(1+tanh(x/2)); result f16x2
__device__ __forceinline__ uint32_t silu2h(float x0, float x1) {
    uint32_t hx = packh(0.5f * x0, 0.5f * x1);
    uint32_t t, opt, r;
    asm("tanh.approx.f16x2 %0, %1;" : "=r"(t) : "r"(hx));
    asm("add.f16x2 %0, %1, %2;" : "=r"(opt) : "r"(t), "r"(0x3C003C00u));
    asm("mul.f16x2 %0, %1, %2;" : "=r"(r) : "r"(hx), "r"(opt));
    return r;
}
__device__ __forceinline__ uint32_t smem_u32(const void* p) {
    uint32_t a;
    asm("{ .reg .u64 t; cvta.to.shared.u64 t, %1; cvt.u32.u64 %0, t; }" : "=r"(a) : "l"(p));
    return a;
}
__device__ __forceinline__ void cpa16(uint32_t saddr, const void* g) {
    asm volatile("cp.async.cg.shared.global [%0], [%1], 16;\n" ::"r"(saddr), "l"(g));
}
__device__ __forceinline__ void cpcommit() { asm volatile("cp.async.commit_group;\n"); }
template <int N>
__device__ __forceinline__ void cpwait() { asm volatile("cp.async.wait_group %0;\n" ::"n"(N)); }

__device__ __forceinline__ void mma16(float d[4], const uint32_t a[4],
                                      const uint32_t b[2], const float c[4]) {
    asm volatile(
        "mma.sync.aligned.m16n8k16.row.col.f32.f16.f16.f32 "
        "{%0,%1,%2,%3}, {%4,%5,%6,%7}, {%8,%9}, {%10,%11,%12,%13};\n"
        : "=f"(d[0]), "=f"(d[1]), "=f"(d[2]), "=f"(d[3])
        : "r"(a[0]), "r"(a[1]), "r"(a[2]), "r"(a[3]),
          "r"(b[0]), "r"(b[1]),
          "f"(c[0]), "f"(c[1]), "f"(c[2]), "f"(c[3]));
}
__device__ __forceinline__ void mma8(float d[4], const uint32_t a[4],
                                     const uint32_t b[2], const float c[4]) {
    asm volatile(
        "mma.sync.aligned.m16n8k8.row.col.f32.tf32.tf32.f32 "
        "{%0,%1,%2,%3}, {%4,%5,%6,%7}, {%8,%9}, {%10,%11,%12,%13};\n"
        : "=f"(d[0]), "=f"(d[1]), "=f"(d[2]), "=f"(d[3])
        : "r"(a[0]), "r"(a[1]), "r"(a[2]), "r"(a[3]),
          "r"(b[0]), "r"(b[1]),
          "f"(c[0]), "f"(c[1]), "f"(c[2]), "f"(c[3]));
}

// ============================================================================
// Kernel 0: build fp16 B-fragment images (W1/W2/W3) + tf32 U-fragment images.
// ============================================================================
__global__ void prep_kernel(const float* __restrict__ W1, const float* __restrict__ W2,
                            const float* __restrict__ W3, const float* __restrict__ U) {
    __half* gh = (__half*)g_wfrag;
    int idx = blockIdx.x * 256 + threadIdx.x;
    if (idx < 65536) {                    // W2 [256k x 256n]
        int k = idx >> 8, n = idx & 255;
        int chunk = k >> 5, ks = (k >> 4) & 1, kl = k & 15;
        int b_idx = kl >> 3, q = (kl & 7) >> 1, par = kl & 1;
        int wn = n >> 5, nt = (n >> 3) & 3, g = n & 7;
        int slot = chunk * 2048 + ((ks * 8 + wn) * 4 + nt) * 32 + g * 4 + q;
        gh[slot * 4 + b_idx * 2 + par] = __float2half_rn(W2[idx]);
    } else if (idx < 69632) {             // W1 [16k x 256n]
        int t = idx - 65536;
        int k = t >> 8, n = t & 255;
        int b_idx = k >> 3, q = (k & 7) >> 1, par = k & 1;
        int wn = n >> 5, nt = (n >> 3) & 3, g = n & 7;
        int slot = (wn * 4 + nt) * 32 + g * 4 + q;
        gh[65536 + slot * 4 + b_idx * 2 + par] = __float2half_rn(W1[t]);
    } else if (idx < 73728) {             // W3 [256k x 16n]
        int t = idx - 69632;
        int k = t >> 4, n = t & 15;
        int ks = k >> 4, kl = k & 15;
        int b_idx = kl >> 3, q = (kl & 7) >> 1, par = kl & 1;
        int nt = n >> 3, g = n & 7;
        int slot = (ks * 2 + nt) * 32 + g * 4 + q;
        gh[69632 + slot * 4 + b_idx * 2 + par] = __float2half_rn(W3[t]);
    } else if (idx < 74752) {             // ufA: 1024 float2 (z@U, k=128,n=16)
        int t = idx - 73728;
        int lane = t & 31, nt = (t >> 5) & 1, kk = t >> 6;
        int g = lane >> 2, q = lane & 3;
        g_ufA[t * 2]     = nan0(U[(kk * 8 + q) * RR + nt * 8 + g]);
        g_ufA[t * 2 + 1] = nan0(U[(kk * 8 + q + 4) * RR + nt * 8 + g]);
    } else if (idx < 75776) {             // ufB: 1024 float2 (cs@Ut, k=16,n=128)
        int t = idx - 74752;
        int lane = t & 31, nt = (t >> 5) & 15, ks = t >> 9;
        int g = lane >> 2, q = lane & 3;
        g_ufB[t * 2]     = nan0(U[(nt * 8 + g) * RR + ks * 8 + q]);
        g_ufB[t * 2 + 1] = nan0(U[(nt * 8 + g) * RR + ks * 8 + q + 4]);
    }
}

// ============================================================================
// Fused kernel: MLP (fp16 mma) + closed-form dynamics (tf32 mma).
// 64 rows/CTA, 512 threads, 2 CTAs/SM.
// ============================================================================
__global__ void __launch_bounds__(512, 2) fused_kernel(
    const float* __restrict__ pt, const float* __restrict__ z,
    const float* __restrict__ dt_norm_g, const float* __restrict__ U,
    const float* __restrict__ b1, const float* __restrict__ b2,
    const float* __restrict__ b3, float* __restrict__ out) {
    extern __shared__ char smc[];
    __shared__ float b1s[256], b2s[256], b3s[16], cn2s[16];

    const int tid = threadIdx.x;
    const int wid = tid >> 5, lane = tid & 31;
    const int g = lane >> 2, q = lane & 3;
    const int r0 = blockIdx.x * MTILE;
    const uint32_t sb = smem_u32(smc);
    const char* gw = (const char*)g_wfrag;

    // group 0: W1 frags + W3 frags
    cpa16(sb + OFF_W1F + tid * 16, gw + 131072 + tid * 16);
    cpa16(sb + OFF_W3F + tid * 16, gw + 139264 + tid * 16);
    cpcommit();
    // groups 1,2: W2 chunks 0,1
#pragma unroll
    for (int c = 0; c < 2; c++) {
#pragma unroll
        for (int i = 0; i < 2; i++) {
            int idx = tid + i * 512;
            cpa16(sb + OFF_RING + c * 16384 + idx * 16, gw + (size_t)c * 16384 + idx * 16);
        }
        cpcommit();
    }

    // --- stage x as fp16 A-frags (nan0) ---
    __half* xf = (__half*)(smc + OFF_XF);
#pragma unroll
    for (int i = 0; i < 2; i++) {
        int idx = tid + i * 512;
        int r = idx >> 4, c = idx & 15;
        float v = nan0(pt[(size_t)(r0 + r) * GD + c]);
        int rr = r & 15, rb = r >> 4;
        int gg = rr & 7, hi8 = rr >> 3;
        int qq = (c & 7) >> 1, par = c & 1;
        int a_idx = ((c >= 8) ? 2 : 0) + hi8;
        int ln = gg * 4 + qq;
        xf[(rb * 32 + ln) * 8 + a_idx * 2 + par] = __float2half_rn(v);
    }
    if (tid < 256) {
        b1s[tid] = b1[tid];
        b2s[tid] = b2[tid];
    }
    if (tid < 16) {
        b3s[tid] = b3[tid];
        float s = 0.f;
        for (int j = 0; j < ZD; j++) {
            float u = nan0(U[j * RR + tid]);
            s += u * u;
        }
        cn2s[tid] = s;
    }
    cpwait<2>();     // W1/W3 ready; chunks 0,1 in flight
    __syncthreads();

    const int wm = wid >> 3, wn = wid & 7;   // 2 x 8 warps (GEMM1/2)

    // ================= GEMM1: h1 = silu(x @ W1 + b1) -> h1 A-frags =========
#pragma unroll
    for (int mt = 0; mt < 2; mt++) {
        int rb = wm * 2 + mt;
        uint4 Av = *(const uint4*)(smc + OFF_XF + (rb * 32 + lane) * 16);
        uint32_t A[4] = {Av.x, Av.y, Av.z, Av.w};
#pragma unroll
        for (int nt = 0; nt < 4; nt++) {
            float acc[4] = {0.f, 0.f, 0.f, 0.f};
            uint2 Bv = *(const uint2*)(smc + OFF_W1F + ((wn * 4 + nt) * 32 + lane) * 8);
            uint32_t B[2] = {Bv.x, Bv.y};
            mma16(acc, A, B, acc);
            int ntile = wn * 4 + nt, cb = ntile * 8;
            float bx = b1s[cb + 2 * q], by = b1s[cb + 2 * q + 1];
            int kk = ntile >> 1, half = ntile & 1;
            uint2 pk = make_uint2(silu2h(acc[0] + bx, acc[1] + by),
                                  silu2h(acc[2] + bx, acc[3] + by));
            *(uint2*)(smc + OFF_H1F + ((rb * 16 + kk) * 32 + lane) * 16 + half * 8) = pk;
        }
    }
    __syncthreads();

    // ================= GEMM2: h2 = silu(h1 @ W2 + b2), 8 chunks K=32 =======
    float acc[2][4][4];
#pragma unroll
    for (int mt = 0; mt < 2; mt++)
#pragma unroll
        for (int nt = 0; nt < 4; nt++)
#pragma unroll
            for (int i = 0; i < 4; i++) acc[mt][nt][i] = 0.f;

    for (int c = 0; c < 8; c++) {
        if (c == 7) cpwait<0>(); else cpwait<1>();
        __syncthreads();
        if (c + 2 < 8) {
            int j = c + 2;
            int slot = j - (j / 3) * 3;
#pragma unroll
            for (int i = 0; i < 2; i++) {
                int idx = tid + i * 512;
                cpa16(sb + OFF_RING + slot * 16384 + idx * 16,
                      gw + (size_t)j * 16384 + idx * 16);
            }
            cpcommit();
        }
        const char* wb = smc + OFF_RING + (c - (c / 3) * 3) * 16384;
#pragma unroll
        for (int ks = 0; ks < 2; ks++) {
            int kk = c * 2 + ks;
            uint4 A0v = *(const uint4*)(smc + OFF_H1F + (((wm * 2 + 0) * 16 + kk) * 32 + lane) * 16);
            uint4 A1v = *(const uint4*)(smc + OFF_H1F + (((wm * 2 + 1) * 16 + kk) * 32 + lane) * 16);
            uint32_t A0[4] = {A0v.x, A0v.y, A0v.z, A0v.w};
            uint32_t A1[4] = {A1v.x, A1v.y, A1v.z, A1v.w};
#pragma unroll
            for (int nt = 0; nt < 4; nt++) {
                uint2 Bv = *(const uint2*)(wb + (((ks * 8 + wn) * 4 + nt) * 32 + lane) * 8);
                uint32_t B[2] = {Bv.x, Bv.y};
                mma16(acc[0][nt], A0, B, acc[0][nt]);
                mma16(acc[1][nt], A1, B, acc[1][nt]);
            }
        }
    }
    __syncthreads();   // ring fully consumed

    // --- issue z load into (dead) ring region: zs stride 132, raw (inputs finite)
    {
        float* zs = (float*)(smc + OFF_ZS);
#pragma unroll
        for (int i = 0; i < 4; i++) {
            int idx = tid + i * 512;                // 2048 x float4
            int row = idx >> 5, c4 = (idx & 31) << 2;
            cpa16(smem_u32(&zs[row * 132 + c4]), &z[(size_t)(r0 + row) * ZD + c4]);
        }
        cpcommit();
    }

    // epilogue -> h2 A-frags (overlay OFF_H1F)
#pragma unroll
    for (int mt = 0; mt < 2; mt++) {
        int rb = wm * 2 + mt;
#pragma unroll
        for (int nt = 0; nt < 4; nt++) {
            int ntile = wn * 4 + nt, cb = ntile * 8;
            float bx = b2s[cb + 2 * q], by = b2s[cb + 2 * q + 1];
            int kk = ntile >> 1, half = ntile & 1;
            uint2 pk = make_uint2(silu2h(acc[mt][nt][0] + bx, acc[mt][nt][1] + by),
                                  silu2h(acc[mt][nt][2] + bx, acc[mt][nt][3] + by));
            *(uint2*)(smc + OFF_H1F + ((rb * 16 + kk) * 32 + lane) * 16 + half * 8) = pk;
        }
    }
    __syncthreads();

    // ================= GEMM3: h = h2 @ W3 (K-split 2 x N-split 2) ==========
    float* hp = (float*)(smc + OFF_HP);   // [2][64][20] fp32 partials (over XF+W1F)
    {
        int rb = wid & 3, wk = (wid >> 2) & 1, nt3 = wid >> 3;
        float a3[4] = {0.f, 0.f, 0.f, 0.f};
#pragma unroll
        for (int ksl = 0; ksl < 8; ksl++) {
            int kk = wk * 8 + ksl;
            uint4 Av = *(const uint4*)(smc + OFF_H1F + ((rb * 16 + kk) * 32 + lane) * 16);
            uint32_t A[4] = {Av.x, Av.y, Av.z, Av.w};
            uint2 Bv = *(const uint2*)(smc + OFF_W3F + ((kk * 2 + nt3) * 32 + lane) * 8);
            uint32_t B[2] = {Bv.x, Bv.y};
            mma16(a3, A, B, a3);
        }
        int c0 = nt3 * 8 + 2 * q;
        *(float2*)&hp[(wk * 64 + rb * 16 + g) * 20 + c0]     = make_float2(a3[0], a3[1]);
        *(float2*)&hp[(wk * 64 + rb * 16 + g + 8) * 20 + c0] = make_float2(a3[2], a3[3]);
    }
    __syncthreads();   // hp ready; h2f + W3F reads complete

    // --- issue ufA/ufB loads into dead h2f / W3F regions ---
    cpa16(sb + OFF_UFA + tid * 16, (const char*)g_ufA + tid * 16);
    cpa16(sb + OFF_UFB + tid * 16, (const char*)g_ufB + tid * 16);
    cpcommit();

    // ================= per-row epilogue: lamg, d -> smem =================
    float* ds = (float*)(smc + OFF_DS);
    float* lg = (float*)(smc + OFF_LG);
    if (tid < 64) {
        int row = tid;
        float s[16], fro2 = 0.f;
#pragma unroll
        for (int r = 0; r < 16; r++) {
            float v = b3s[r] + hp[row * 20 + r] + hp[(64 + row) * 20 + r];
            float sr = 2.f / (1.f + __expf(-v));
            s[r] = sr;
            fro2 += sr * sr * cn2s[r];
        }
        float fro = sqrtf(fro2);
        float scale = fminf(2.2627416997969522f / fmaxf(fro, 1e-9f), 1.f);

        float v = dt_norm_g[r0 + row];
        if (isnan(v)) v = 0.f;
        v = fminf(fmaxf(v, 0.f), 1.f);
        float logdt = fminf(-3.f + v * 11.f, 2.7781512503836436f);   // log10(600)
        float dt = fmaxf(expf(logdt * 2.302585092994046f), 1e-30f);
        float lamg = expf(-0.1f * dt);
        lg[row] = lamg;
#pragma unroll
        for (int r = 0; r < 16; r++) {
            float ss = s[r] * scale;
            float lp = expf(-ss * ss * dt) * lamg;
            ds[row * 20 + r] = lp - lamg;
        }
    }
    cpwait<0>();       // z + ufA/ufB landed
    __syncthreads();

    const float* zs = (const float*)(smc + OFF_ZS);
    float* cs = (float*)(smc + OFF_CS);
    const char* ufA = smc + OFF_UFA;
    const char* ufB = smc + OFF_UFB;

    // ===== GEMM A: cs[row][r] = d[row][r] * (z @ U)[row][r]  (8 warps) =====
    if (wid < 8) {
        int mt = wid >> 1, nt = wid & 1;
        int rbase = mt * 16, cbase = nt * 8;
        float accA[4] = {0.f, 0.f, 0.f, 0.f};
#pragma unroll
        for (int kk = 0; kk < 16; kk++) {
            int k0 = kk * 8;
            uint32_t a[4] = {
                fbits(zs[(rbase + g) * 132 + k0 + q]),
                fbits(zs[(rbase + g + 8) * 132 + k0 + q]),
                fbits(zs[(rbase + g) * 132 + k0 + q + 4]),
                fbits(zs[(rbase + g + 8) * 132 + k0 + q + 4])};
            uint2 bv = *(const uint2*)(ufA + ((kk * 2 + nt) * 32 + lane) * 8);
            uint32_t b[2] = {bv.x, bv.y};
            mma8(accA, a, b, accA);
        }
        int row0 = rbase + g, row1 = rbase + g + 8;
        int c0 = cbase + 2 * q, c1 = c0 + 1;
        cs[row0 * 20 + c0] = accA[0] * ds[row0 * 20 + c0];
        cs[row0 * 20 + c1] = accA[1] * ds[row0 * 20 + c1];
        cs[row1 * 20 + c0] = accA[2] * ds[row1 * 20 + c0];
        cs[row1 * 20 + c1] = accA[3] * ds[row1 * 20 + c1];
    }
    __syncthreads();

    // ===== GEMM B + identity, direct to global (16 warps) =====
    {
        int mt = wid & 3, wnb = wid >> 2;     // mt: 16-row tile, wnb: 32-col group
        int rbase = mt * 16;
        float accB[4][4];
#pragma unroll
        for (int nt = 0; nt < 4; nt++)
#pragma unroll
            for (int i = 0; i < 4; i++) accB[nt][i] = 0.f;
#pragma unroll
        for (int ks = 0; ks < 2; ks++) {
            int k0 = ks * 8;
            uint32_t a[4] = {
                fbits(cs[(rbase + g) * 20 + k0 + q]),
                fbits(cs[(rbase + g + 8) * 20 + k0 + q]),
                fbits(cs[(rbase + g) * 20 + k0 + q + 4]),
                fbits(cs[(rbase + g + 8) * 20 + k0 + q + 4])};
#pragma unroll
            for (int nt = 0; nt < 4; nt++) {
                uint2 bv = *(const uint2*)(ufB + ((ks * 16 + wnb * 4 + nt) * 32 + lane) * 8);
                uint32_t b[2] = {bv.x, bv.y};
                mma8(accB[nt], a, b, accB[nt]);
            }
        }
        int row0 = rbase + g, row1 = rbase + g + 8;
        float l0 = lg[row0], l1 = lg[row1];
        size_t gr0 = (size_t)(r0 + row0) * ZD, gr1 = (size_t)(r0 + row1) * ZD;
#pragma unroll
        for (int nt = 0; nt < 4; nt++) {
            int cb = (wnb * 4 + nt) * 8;
            int c0 = cb + 2 * q;
            float2 z0 = *(const float2*)&zs[row0 * 132 + c0];
            float2 o0;
            o0.x = l0 * z0.x + accB[nt][0];
            o0.y = l0 * z0.y + accB[nt][1];
            *(float2*)&out[gr0 + c0] = o0;
            float2 z1 = *(const float2*)&zs[row1 * 132 + c0];
            float2 o1;
            o1.x = l1 * z1.x + accB[nt][2];
            o1.y = l1 * z1.y + accB[nt][3];
            *(float2*)&out[gr1 + c0] = o1;
        }
    }
}

extern "C" void kernel_launch(void* const* d_in, const int* in_sizes, int n_in,
                              void* d_out, int out_size) {
    const float* pt      = (const float*)d_in[0];
    const float* z       = (const float*)d_in[1];
    const float* dt_norm = (const float*)d_in[2];
    const float* base_U  = (const float*)d_in[3];
    const float* W1      = (const float*)d_in[4];
    const float* b1      = (const float*)d_in[5];
    const float* W2      = (const float*)d_in[6];
    const float* b2      = (const float*)d_in[7];
    const float* W3      = (const float*)d_in[8];
    const float* b3      = (const float*)d_in[9];
    float* out = (float*)d_out;

    cudaFuncSetAttribute(fused_kernel, cudaFuncAttributeMaxDynamicSharedMemorySize, SMEM_BYTES);

    prep_kernel<<<296, 256>>>(W1, W2, W3, base_U);
    fused_kernel<<<NBLK, 512, SMEM_BYTES>>>(pt, z, dt_norm, base_U, b1, b2, b3, out);
}

// round 11
// speedup vs baseline: 1.3666x; 1.0438x over previous
#include <cuda_runtime.h>
#include <cuda_fp16.h>
#include <cstdint>
#include <math.h>

#define BATCH 262144
#define GD 16
#define HID 256
#define RR 16
#define ZD 128
#define MTILE 64
#define NBLK (BATCH / MTILE)

// ---- fused kernel dynamic smem layout (bytes) ----
#define OFF_XF   0        // x A-frags 2048        [hp overlays XF+W1F in GEMM3]
#define OFF_W1F  2048     // W1 B-frags 8192
#define OFF_W3F  10240    // W3 B-frags 8192       [ufB overlays after GEMM3]
#define OFF_H1F  18432    // h1/h2 A-frags 32768   [ufA overlays after GEMM3]
#define OFF_RING 51200    // W2 ring 3x16384=49152 [zs/cs/ds/lg overlay after GEMM2]
#define SMEM_BYTES 100352
// overlays
#define OFF_HP   0            // 2*64*20*4 = 10240 (GEMM3 partials)
#define OFF_UFB  10240        // 8192
#define OFF_UFA  18432        // 8192
#define OFF_ZS   51200        // 64*132*4 = 33792
#define OFF_CS   84992        // 64*20*4  = 5120
#define OFF_DS   90112        // 64*20*4  = 5120
#define OFF_LG   95232        // 256

// device-global weight images (allocation-free scratch)
__device__ __align__(256) uint32_t g_wfrag[36864];  // W2 8x16KB, W1 @u32 32768, W3 @u32 34816
__device__ __align__(256) float g_ufA[2048];
__device__ __align__(256) float g_ufB[2048];

__device__ __forceinline__ uint32_t fbits(float x) { return __float_as_uint(x); }
__device__ __forceinline__ float nan0(float v) { return isfinite(v) ? v : 0.f; }
__device__ __forceinline__ uint32_t packh(float lo, float hi) {
    uint32_t u;
    asm("cvt.rn.f16x2.f32 %0, %1, %2;" : "=r"(u) : "f"(hi), "f"(lo));
    return u;
}
// silu pair via ONE MUFU: silu(x) = (x/2)*(1+tanh(x/2)); result f16x2
__device__ __forceinline__ uint32_t silu2h(float x0, float x1) {
    uint32_t hx = packh(0.5f * x0, 0.5f * x1);
    uint32_t t, opt, r;
    asm("tanh.approx.f16x2 %0, %1;" : "=r"(t) : "r"(hx));
    asm("add.f16x2 %0, %1, %2;" : "=r"(opt) : "r"(t), "r"(0x3C003C00u));
    asm("mul.f16x2 %0, %1, %2;" : "=r"(r) : "r"(hx), "r"(opt));
    return r;
}
__device__ __forceinline__ uint32_t smem_u32(const void* p) {
    uint32_t a;
    asm("{ .reg .u64 t; cvta.to.shared.u64 t, %1; cvt.u32.u64 %0, t; }" : "=r"(a) : "l"(p));
    return a;
}
__device__ __forceinline__ void cpa16(uint32_t saddr, const void* g) {
    asm volatile("cp.async.cg.shared.global [%0], [%1], 16;\n" ::"r"(saddr), "l"(g));
}
__device__ __forceinline__ void cpcommit() { asm volatile("cp.async.commit_group;\n"); }
template <int N>
__device__ __forceinline__ void cpwait() { asm volatile("cp.async.wait_group %0;\n" ::"n"(N)); }

__device__ __forceinline__ void mma16(float d[4], const uint32_t a[4],
                                      const uint32_t b[2], const float c[4]) {
    asm volatile(
        "mma.sync.aligned.m16n8k16.row.col.f32.f16.f16.f32 "
        "{%0,%1,%2,%3}, {%4,%5,%6,%7}, {%8,%9}, {%10,%11,%12,%13};\n"
        : "=f"(d[0]), "=f"(d[1]), "=f"(d[2]), "=f"(d[3])
        : "r"(a[0]), "r"(a[1]), "r"(a[2]), "r"(a[3]),
          "r"(b[0]), "r"(b[1]),
          "f"(c[0]), "f"(c[1]), "f"(c[2]), "f"(c[3]));
}
__device__ __forceinline__ void mma8(float d[4], const uint32_t a[4],
                                     const uint32_t b[2], const float c[4]) {
    asm volatile(
        "mma.sync.aligned.m16n8k8.row.col.f32.tf32.tf32.f32 "
        "{%0,%1,%2,%3}, {%4,%5,%6,%7}, {%8,%9}, {%10,%11,%12,%13};\n"
        : "=f"(d[0]), "=f"(d[1]), "=f"(d[2]), "=f"(d[3])
        : "r"(a[0]), "r"(a[1]), "r"(a[2]), "r"(a[3]),
          "r"(b[0]), "r"(b[1]),
          "f"(c[0]), "f"(c[1]), "f"(c[2]), "f"(c[3]));
}

// ============================================================================
// Kernel 0: build PAIRED fragment images.
// W1/W2: uint4 slot = {B-frag nt even (8B), B-frag nt odd (8B)}
// ufA:   uint4 slot = {tf32 B-frag kk even, kk odd}
// ufB:   uint4 slot = {tf32 B-frag nt even, nt odd}
// W3: unchanged uint2 slots (nt3 is a warp split in GEMM3).
// ============================================================================
__global__ void prep_kernel(const float* __restrict__ W1, const float* __restrict__ W2,
                            const float* __restrict__ W3, const float* __restrict__ U) {
    __half* gh = (__half*)g_wfrag;
    int idx = blockIdx.x * 256 + threadIdx.x;
    if (idx < 65536) {                    // W2 [256k x 256n]
        int k = idx >> 8, n = idx & 255;
        int chunk = k >> 5, ks = (k >> 4) & 1, kl = k & 15;
        int b_idx = kl >> 3, q = (kl & 7) >> 1, par = kl & 1;
        int wn = n >> 5, nt = (n >> 3) & 3, g = n & 7;
        int ntp = nt >> 1, sub = nt & 1;
        int slot4 = chunk * 1024 + ((ks * 8 + wn) * 2 + ntp) * 32 + g * 4 + q;
        gh[slot4 * 8 + sub * 4 + b_idx * 2 + par] = __float2half_rn(W2[idx]);
    } else if (idx < 69632) {             // W1 [16k x 256n]
        int t = idx - 65536;
        int k = t >> 8, n = t & 255;
        int b_idx = k >> 3, q = (k & 7) >> 1, par = k & 1;
        int wn = n >> 5, nt = (n >> 3) & 3, g = n & 7;
        int ntp = nt >> 1, sub = nt & 1;
        int slot4 = (wn * 2 + ntp) * 32 + g * 4 + q;
        gh[65536 + slot4 * 8 + sub * 4 + b_idx * 2 + par] = __float2half_rn(W1[t]);
    } else if (idx < 73728) {             // W3 [256k x 16n] (unchanged layout)
        int t = idx - 69632;
        int k = t >> 4, n = t & 15;
        int ks = k >> 4, kl = k & 15;
        int b_idx = kl >> 3, q = (kl & 7) >> 1, par = kl & 1;
        int nt = n >> 3, g = n & 7;
        int slot = (ks * 2 + nt) * 32 + g * 4 + q;
        gh[69632 + slot * 4 + b_idx * 2 + par] = __float2half_rn(W3[t]);
    } else if (idx < 74752) {             // ufA: kk-paired tf32 frags (z@U)
        int t = idx - 73728;
        int lane = t & 31, nt = (t >> 5) & 1, kk = t >> 6;
        int g = lane >> 2, q = lane & 3;
        int b4 = ((kk >> 1) * 2 + nt) * 32 + lane;
        g_ufA[b4 * 4 + (kk & 1) * 2]     = nan0(U[(kk * 8 + q) * RR + nt * 8 + g]);
        g_ufA[b4 * 4 + (kk & 1) * 2 + 1] = nan0(U[(kk * 8 + q + 4) * RR + nt * 8 + g]);
    } else if (idx < 75776) {             // ufB: nt-paired tf32 frags (cs@Ut)
        int t = idx - 74752;
        int lane = t & 31, ntt = (t >> 5) & 15, ks = t >> 9;
        int g = lane >> 2, q = lane & 3;
        int wnb = ntt >> 2, ntl = ntt & 3, ntp = ntl >> 1, sub = ntl & 1;
        int b4 = (ks * 8 + wnb * 2 + ntp) * 32 + lane;
        g_ufB[b4 * 4 + sub * 2]     = nan0(U[(ntt * 8 + g) * RR + ks * 8 + q]);
        g_ufB[b4 * 4 + sub * 2 + 1] = nan0(U[(ntt * 8 + g) * RR + ks * 8 + q + 4]);
    }
}

// ============================================================================
// Fused kernel: MLP (fp16 mma) + closed-form dynamics (tf32 mma).
// 64 rows/CTA, 512 threads, 2 CTAs/SM. Paired LDS.128/STS.128 everywhere.
// ============================================================================
__global__ void __launch_bounds__(512, 2) fused_kernel(
    const float* __restrict__ pt, const float* __restrict__ z,
    const float* __restrict__ dt_norm_g, const float* __restrict__ U,
    const float* __restrict__ b1, const float* __restrict__ b2,
    const float* __restrict__ b3, float* __restrict__ out) {
    extern __shared__ char smc[];
    __shared__ float b1s[256], b2s[256], b3s[16], cn2s[16];

    const int tid = threadIdx.x;
    const int wid = tid >> 5, lane = tid & 31;
    const int g = lane >> 2, q = lane & 3;
    const int r0 = blockIdx.x * MTILE;
    const uint32_t sb = smem_u32(smc);
    const char* gw = (const char*)g_wfrag;

    // group 0: W1 frags + W3 frags
    cpa16(sb + OFF_W1F + tid * 16, gw + 131072 + tid * 16);
    cpa16(sb + OFF_W3F + tid * 16, gw + 139264 + tid * 16);
    cpcommit();
    // groups 1,2: W2 chunks 0,1
#pragma unroll
    for (int c = 0; c < 2; c++) {
#pragma unroll
        for (int i = 0; i < 2; i++) {
            int idx = tid + i * 512;
            cpa16(sb + OFF_RING + c * 16384 + idx * 16, gw + (size_t)c * 16384 + idx * 16);
        }
        cpcommit();
    }

    // --- stage x as fp16 A-frags (nan0) ---
    __half* xf = (__half*)(smc + OFF_XF);
#pragma unroll
    for (int i = 0; i < 2; i++) {
        int idx = tid + i * 512;
        int r = idx >> 4, c = idx & 15;
        float v = nan0(pt[(size_t)(r0 + r) * GD + c]);
        int rr = r & 15, rb = r >> 4;
        int gg = rr & 7, hi8 = rr >> 3;
        int qq = (c & 7) >> 1, par = c & 1;
        int a_idx = ((c >= 8) ? 2 : 0) + hi8;
        int ln = gg * 4 + qq;
        xf[(rb * 32 + ln) * 8 + a_idx * 2 + par] = __float2half_rn(v);
    }
    if (tid < 256) {
        b1s[tid] = b1[tid];
        b2s[tid] = b2[tid];
    }
    if (tid < 16) {
        b3s[tid] = b3[tid];
        float s = 0.f;
        for (int j = 0; j < ZD; j++) {
            float u = nan0(U[j * RR + tid]);
            s += u * u;
        }
        cn2s[tid] = s;
    }
    cpwait<2>();     // W1/W3 ready; chunks 0,1 in flight
    __syncthreads();

    const int wm = wid >> 3, wn = wid & 7;   // 2 x 8 warps (GEMM1/2)

    // ================= GEMM1: h1 = silu(x @ W1 + b1) -> h1 A-frags =========
#pragma unroll
    for (int mt = 0; mt < 2; mt++) {
        int rb = wm * 2 + mt;
        uint4 Av = *(const uint4*)(smc + OFF_XF + (rb * 32 + lane) * 16);
        uint32_t A[4] = {Av.x, Av.y, Av.z, Av.w};
#pragma unroll
        for (int ntp = 0; ntp < 2; ntp++) {
            uint4 Bp = *(const uint4*)(smc + OFF_W1F + ((wn * 2 + ntp) * 32 + lane) * 16);
            uint32_t B0[2] = {Bp.x, Bp.y}, B1[2] = {Bp.z, Bp.w};
            float a0[4] = {0.f, 0.f, 0.f, 0.f}, a1[4] = {0.f, 0.f, 0.f, 0.f};
            mma16(a0, A, B0, a0);
            mma16(a1, A, B1, a1);
            int nt0 = wn * 4 + 2 * ntp;
            float bx0 = b1s[nt0 * 8 + 2 * q], by0 = b1s[nt0 * 8 + 2 * q + 1];
            float bx1 = b1s[nt0 * 8 + 8 + 2 * q], by1 = b1s[nt0 * 8 + 8 + 2 * q + 1];
            int kk = wn * 2 + ntp;
            uint4 pk;
            pk.x = silu2h(a0[0] + bx0, a0[1] + by0);
            pk.y = silu2h(a0[2] + bx0, a0[3] + by0);
            pk.z = silu2h(a1[0] + bx1, a1[1] + by1);
            pk.w = silu2h(a1[2] + bx1, a1[3] + by1);
            *(uint4*)(smc + OFF_H1F + ((rb * 16 + kk) * 32 + lane) * 16) = pk;
        }
    }
    __syncthreads();

    // ================= GEMM2: h2 = silu(h1 @ W2 + b2), 8 chunks K=32 =======
    float acc[2][4][4];
#pragma unroll
    for (int mt = 0; mt < 2; mt++)
#pragma unroll
        for (int nt = 0; nt < 4; nt++)
#pragma unroll
            for (int i = 0; i < 4; i++) acc[mt][nt][i] = 0.f;

    for (int c = 0; c < 8; c++) {
        if (c == 7) cpwait<0>(); else cpwait<1>();
        __syncthreads();
        if (c + 2 < 8) {
            int j = c + 2;
            int slot = j - (j / 3) * 3;
#pragma unroll
            for (int i = 0; i < 2; i++) {
                int idx = tid + i * 512;
                cpa16(sb + OFF_RING + slot * 16384 + idx * 16,
                      gw + (size_t)j * 16384 + idx * 16);
            }
            cpcommit();
        }
        const char* wb = smc + OFF_RING + (c - (c / 3) * 3) * 16384;
#pragma unroll
        for (int ks = 0; ks < 2; ks++) {
            int kk = c * 2 + ks;
            uint4 A0v = *(const uint4*)(smc + OFF_H1F + (((wm * 2 + 0) * 16 + kk) * 32 + lane) * 16);
            uint4 A1v = *(const uint4*)(smc + OFF_H1F + (((wm * 2 + 1) * 16 + kk) * 32 + lane) * 16);
            uint32_t A0[4] = {A0v.x, A0v.y, A0v.z, A0v.w};
            uint32_t A1[4] = {A1v.x, A1v.y, A1v.z, A1v.w};
#pragma unroll
            for (int ntp = 0; ntp < 2; ntp++) {
                uint4 Bp = *(const uint4*)(wb + (((ks * 8 + wn) * 2 + ntp) * 32 + lane) * 16);
                uint32_t B0[2] = {Bp.x, Bp.y}, B1[2] = {Bp.z, Bp.w};
                mma16(acc[0][2 * ntp],     A0, B0, acc[0][2 * ntp]);
                mma16(acc[1][2 * ntp],     A1, B0, acc[1][2 * ntp]);
                mma16(acc[0][2 * ntp + 1], A0, B1, acc[0][2 * ntp + 1]);
                mma16(acc[1][2 * ntp + 1], A1, B1, acc[1][2 * ntp + 1]);
            }
        }
    }
    __syncthreads();   // ring fully consumed

    // --- issue z load into (dead) ring region: zs stride 132 (inputs finite)
    {
        float* zs = (float*)(smc + OFF_ZS);
#pragma unroll
        for (int i = 0; i < 4; i++) {
            int idx = tid + i * 512;                // 2048 x float4
            int row = idx >> 5, c4 = (idx & 31) << 2;
            cpa16(smem_u32(&zs[row * 132 + c4]), &z[(size_t)(r0 + row) * ZD + c4]);
        }
        cpcommit();
    }

    // epilogue -> h2 A-frags (overlay OFF_H1F), paired STS.128
#pragma unroll
    for (int mt = 0; mt < 2; mt++) {
        int rb = wm * 2 + mt;
#pragma unroll
        for (int ntp = 0; ntp < 2; ntp++) {
            int nt0 = 2 * ntp, nt1 = nt0 + 1;
            int cb0 = (wn * 4 + nt0) * 8, cb1 = (wn * 4 + nt1) * 8;
            float bx0 = b2s[cb0 + 2 * q], by0 = b2s[cb0 + 2 * q + 1];
            float bx1 = b2s[cb1 + 2 * q], by1 = b2s[cb1 + 2 * q + 1];
            int kk = wn * 2 + ntp;
            uint4 pk;
            pk.x = silu2h(acc[mt][nt0][0] + bx0, acc[mt][nt0][1] + by0);
            pk.y = silu2h(acc[mt][nt0][2] + bx0, acc[mt][nt0][3] + by0);
            pk.z = silu2h(acc[mt][nt1][0] + bx1, acc[mt][nt1][1] + by1);
            pk.w = silu2h(acc[mt][nt1][2] + bx1, acc[mt][nt1][3] + by1);
            *(uint4*)(smc + OFF_H1F + ((rb * 16 + kk) * 32 + lane) * 16) = pk;
        }
    }
    __syncthreads();

    // ================= GEMM3: h = h2 @ W3 (K-split 2 x N-split 2) ==========
    float* hp = (float*)(smc + OFF_HP);   // [2][64][20] fp32 partials (over XF+W1F)
    {
        int rb = wid & 3, wk = (wid >> 2) & 1, nt3 = wid >> 3;
        float a3[4] = {0.f, 0.f, 0.f, 0.f};
#pragma unroll
        for (int ksl = 0; ksl < 8; ksl++) {
            int kk = wk * 8 + ksl;
            uint4 Av = *(const uint4*)(smc + OFF_H1F + ((rb * 16 + kk) * 32 + lane) * 16);
            uint32_t A[4] = {Av.x, Av.y, Av.z, Av.w};
            uint2 Bv = *(const uint2*)(smc + OFF_W3F + ((kk * 2 + nt3) * 32 + lane) * 8);
            uint32_t B[2] = {Bv.x, Bv.y};
            mma16(a3, A, B, a3);
        }
        int c0 = nt3 * 8 + 2 * q;
        *(float2*)&hp[(wk * 64 + rb * 16 + g) * 20 + c0]     = make_float2(a3[0], a3[1]);
        *(float2*)&hp[(wk * 64 + rb * 16 + g + 8) * 20 + c0] = make_float2(a3[2], a3[3]);
    }
    __syncthreads();   // hp ready; h2f + W3F reads complete

    // --- issue ufA/ufB loads into dead h2f / W3F regions ---
    cpa16(sb + OFF_UFA + tid * 16, (const char*)g_ufA + tid * 16);
    cpa16(sb + OFF_UFB + tid * 16, (const char*)g_ufB + tid * 16);
    cpcommit();

    // ================= per-row epilogue: lamg, d -> smem =================
    float* ds = (float*)(smc + OFF_DS);
    float* lg = (float*)(smc + OFF_LG);
    if (tid < 64) {
        int row = tid;
        float s[16], fro2 = 0.f;
#pragma unroll
        for (int r = 0; r < 16; r++) {
            float v = b3s[r] + hp[row * 20 + r] + hp[(64 + row) * 20 + r];
            float sr = 2.f / (1.f + __expf(-v));
            s[r] = sr;
            fro2 += sr * sr * cn2s[r];
        }
        float fro = sqrtf(fro2);
        float scale = fminf(2.2627416997969522f / fmaxf(fro, 1e-9f), 1.f);

        float v = dt_norm_g[r0 + row];
        if (isnan(v)) v = 0.f;
        v = fminf(fmaxf(v, 0.f), 1.f);
        float logdt = fminf(-3.f + v * 11.f, 2.7781512503836436f);   // log10(600)
        float dt = fmaxf(expf(logdt * 2.302585092994046f), 1e-30f);
        float lamg = expf(-0.1f * dt);
        lg[row] = lamg;
#pragma unroll
        for (int r = 0; r < 16; r++) {
            float ss = s[r] * scale;
            float lp = expf(-ss * ss * dt) * lamg;
            ds[row * 20 + r] = lp - lamg;
        }
    }
    cpwait<0>();       // z + ufA/ufB landed
    __syncthreads();

    const float* zs = (const float*)(smc + OFF_ZS);
    float* cs = (float*)(smc + OFF_CS);
    const char* ufA = smc + OFF_UFA;
    const char* ufB = smc + OFF_UFB;

    // ===== GEMM A: cs[row][r] = d[row][r] * (z @ U)[row][r]  (8 warps) =====
    if (wid < 8) {
        int mt = wid >> 1, nt = wid & 1;
        int rbase = mt * 16, cbase = nt * 8;
        float accA[4] = {0.f, 0.f, 0.f, 0.f};
#pragma unroll
        for (int kp = 0; kp < 8; kp++) {
            uint4 Bv = *(const uint4*)(ufA + ((kp * 2 + nt) * 32 + lane) * 16);
#pragma unroll
            for (int sub = 0; sub < 2; sub++) {
                int k0 = (kp * 2 + sub) * 8;
                uint32_t a[4] = {
                    fbits(zs[(rbase + g) * 132 + k0 + q]),
                    fbits(zs[(rbase + g + 8) * 132 + k0 + q]),
                    fbits(zs[(rbase + g) * 132 + k0 + q + 4]),
                    fbits(zs[(rbase + g + 8) * 132 + k0 + q + 4])};
                uint32_t b[2] = {sub ? Bv.z : Bv.x, sub ? Bv.w : Bv.y};
                mma8(accA, a, b, accA);
            }
        }
        int row0 = rbase + g, row1 = rbase + g + 8;
        int c0 = cbase + 2 * q, c1 = c0 + 1;
        cs[row0 * 20 + c0] = accA[0] * ds[row0 * 20 + c0];
        cs[row0 * 20 + c1] = accA[1] * ds[row0 * 20 + c1];
        cs[row1 * 20 + c0] = accA[2] * ds[row1 * 20 + c0];
        cs[row1 * 20 + c1] = accA[3] * ds[row1 * 20 + c1];
    }
    __syncthreads();

    // ===== GEMM B + identity, direct to global (16 warps) =====
    {
        int mt = wid & 3, wnb = wid >> 2;     // mt: 16-row tile, wnb: 32-col group
        int rbase = mt * 16;
        float accB[4][4];
#pragma unroll
        for (int nt = 0; nt < 4; nt++)
#pragma unroll
            for (int i = 0; i < 4; i++) accB[nt][i] = 0.f;
#pragma unroll
        for (int ks = 0; ks < 2; ks++) {
            int k0 = ks * 8;
            uint32_t a[4] = {
                fbits(cs[(rbase + g) * 20 + k0 + q]),
                fbits(cs[(rbase + g + 8) * 20 + k0 + q]),
                fbits(cs[(rbase + g) * 20 + k0 + q + 4]),
                fbits(cs[(rbase + g + 8) * 20 + k0 + q + 4])};
#pragma unroll
            for (int ntp = 0; ntp < 2; ntp++) {
                uint4 Bp = *(const uint4*)(ufB + ((ks * 8 + wnb * 2 + ntp) * 32 + lane) * 16);
                uint32_t B0[2] = {Bp.x, Bp.y}, B1[2] = {Bp.z, Bp.w};
                mma8(accB[2 * ntp],     a, B0, accB[2 * ntp]);
                mma8(accB[2 * ntp + 1], a, B1, accB[2 * ntp + 1]);
            }
        }
        int row0 = rbase + g, row1 = rbase + g + 8;
        float l0 = lg[row0], l1 = lg[row1];
        size_t gr0 = (size_t)(r0 + row0) * ZD, gr1 = (size_t)(r0 + row1) * ZD;
#pragma unroll
        for (int nt = 0; nt < 4; nt++) {
            int cb = (wnb * 4 + nt) * 8;
            int c0 = cb + 2 * q;
            float2 z0 = *(const float2*)&zs[row0 * 132 + c0];
            float2 o0;
            o0.x = l0 * z0.x + accB[nt][0];
            o0.y = l0 * z0.y + accB[nt][1];
            *(float2*)&out[gr0 + c0] = o0;
            float2 z1 = *(const float2*)&zs[row1 * 132 + c0];
            float2 o1;
            o1.x = l1 * z1.x + accB[nt][2];
            o1.y = l1 * z1.y + accB[nt][3];
            *(float2*)&out[gr1 + c0] = o1;
        }
    }
}

extern "C" void kernel_launch(void* const* d_in, const int* in_sizes, int n_in,
                              void* d_out, int out_size) {
    const float* pt      = (const float*)d_in[0];
    const float* z       = (const float*)d_in[1];
    const float* dt_norm = (const float*)d_in[2];
    const float* base_U  = (const float*)d_in[3];
    const float* W1      = (const float*)d_in[4];
    const float* b1      = (const float*)d_in[5];
    const float* W2      = (const float*)d_in[6];
    const float* b2      = (const float*)d_in[7];
    const float* W3      = (const float*)d_in[8];
    const float* b3      = (const float*)d_in[9];
    float* out = (float*)d_out;

    cudaFuncSetAttribute(fused_kernel, cudaFuncAttributeMaxDynamicSharedMemorySize, SMEM_BYTES);

    prep_kernel<<<296, 256>>>(W1, W2, W3, base_U);
    fused_kernel<<<NBLK, 512, SMEM_BYTES>>>(pt, z, dt_norm, base_U, b1, b2, b3, out);
}

// round 12
// speedup vs baseline: 1.3997x; 1.0242x over previous
#include <cuda_runtime.h>
#include <cuda_fp16.h>
#include <cstdint>
#include <math.h>

#define BATCH 262144
#define GD 16
#define HID 256
#define RR 16
#define ZD 128
#define MTILE 64
#define NBLK (BATCH / MTILE)

// ---- fused kernel dynamic smem layout (bytes) ----
#define OFF_XF   0        // x A-frags 2048        [hp overlays XF+W1F in GEMM3]
#define OFF_W1F  2048     // W1 B-frags 8192
#define OFF_W3F  10240    // W3 B-frags 8192       [ufB overlays after GEMM3]
#define OFF_H1F  18432    // h1/h2 A-frags 32768   [ufA overlays after GEMM3]
#define OFF_RING 51200    // W2 ring 3x16384=49152 [zs/cs/ds/lg overlay after GEMM2]
#define SMEM_BYTES 100352
// overlays
#define OFF_HP   0            // 2*64*20*4 = 10240 (GEMM3 partials)
#define OFF_UFB  10240        // 8192
#define OFF_UFA  18432        // 8192
#define OFF_ZS   51200        // 64*132*4 = 33792
#define OFF_CS   84992        // 64*20*4  = 5120
#define OFF_DS   90112        // 64*20*4  = 5120
#define OFF_LG   95232        // 256

// device-global weight images (allocation-free scratch)
__device__ __align__(256) uint32_t g_wfrag[36864];  // W2 8x16KB, W1 @u32 32768, W3 @u32 34816
__device__ __align__(256) float g_ufA[2048];
__device__ __align__(256) float g_ufB[2048];

__device__ __forceinline__ uint32_t fbits(float x) { return __float_as_uint(x); }
__device__ __forceinline__ float nan0(float v) { return isfinite(v) ? v : 0.f; }
__device__ __forceinline__ uint32_t packh(float lo, float hi) {
    uint32_t u;
    asm("cvt.rn.f16x2.f32 %0, %1, %2;" : "=r"(u) : "f"(hi), "f"(lo));
    return u;
}
__device__ __forceinline__ uint32_t addh2(uint32_t a, uint32_t b) {
    uint32_t r;
    asm("add.f16x2 %0, %1, %2;" : "=r"(r) : "r"(a), "r"(b));
    return r;
}
// silu on an f16x2 pair via ONE MUFU: silu(x) = (x/2)*(1+tanh(x/2))
__device__ __forceinline__ uint32_t silu16(uint32_t x) {
    uint32_t hx, t, o, r;
    asm("mul.f16x2 %0, %1, %2;" : "=r"(hx) : "r"(x), "r"(0x38003800u));   // x/2
    asm("tanh.approx.f16x2 %0, %1;" : "=r"(t) : "r"(hx));
    asm("add.f16x2 %0, %1, %2;" : "=r"(o) : "r"(t), "r"(0x3C003C00u));    // 1+t
    asm("mul.f16x2 %0, %1, %2;" : "=r"(r) : "r"(hx), "r"(o));
    return r;
}
__device__ __forceinline__ uint32_t smem_u32(const void* p) {
    uint32_t a;
    asm("{ .reg .u64 t; cvta.to.shared.u64 t, %1; cvt.u32.u64 %0, t; }" : "=r"(a) : "l"(p));
    return a;
}
__device__ __forceinline__ void cpa16(uint32_t saddr, const void* g) {
    asm volatile("cp.async.cg.shared.global [%0], [%1], 16;\n" ::"r"(saddr), "l"(g));
}
__device__ __forceinline__ void cpcommit() { asm volatile("cp.async.commit_group;\n"); }
template <int N>
__device__ __forceinline__ void cpwait() { asm volatile("cp.async.wait_group %0;\n" ::"n"(N)); }

// fp16 mma m16n8k16, fp16 accumulate (D/C = 2 regs f16x2)
__device__ __forceinline__ void mma16h(uint32_t d[2], const uint32_t a[4],
                                       const uint32_t b0, const uint32_t b1) {
    asm volatile(
        "mma.sync.aligned.m16n8k16.row.col.f16.f16.f16.f16 "
        "{%0,%1}, {%2,%3,%4,%5}, {%6,%7}, {%0,%1};\n"
        : "+r"(d[0]), "+r"(d[1])
        : "r"(a[0]), "r"(a[1]), "r"(a[2]), "r"(a[3]), "r"(b0), "r"(b1));
}
// fp16 mma m16n8k16, fp32 accumulate (GEMM3)
__device__ __forceinline__ void mma16(float d[4], const uint32_t a[4],
                                      const uint32_t b[2], const float c[4]) {
    asm volatile(
        "mma.sync.aligned.m16n8k16.row.col.f32.f16.f16.f32 "
        "{%0,%1,%2,%3}, {%4,%5,%6,%7}, {%8,%9}, {%10,%11,%12,%13};\n"
        : "=f"(d[0]), "=f"(d[1]), "=f"(d[2]), "=f"(d[3])
        : "r"(a[0]), "r"(a[1]), "r"(a[2]), "r"(a[3]),
          "r"(b[0]), "r"(b[1]),
          "f"(c[0]), "f"(c[1]), "f"(c[2]), "f"(c[3]));
}
// tf32 mma m16n8k8 (dyn phases)
__device__ __forceinline__ void mma8(float d[4], const uint32_t a[4],
                                     const uint32_t b[2], const float c[4]) {
    asm volatile(
        "mma.sync.aligned.m16n8k8.row.col.f32.tf32.tf32.f32 "
        "{%0,%1,%2,%3}, {%4,%5,%6,%7}, {%8,%9}, {%10,%11,%12,%13};\n"
        : "=f"(d[0]), "=f"(d[1]), "=f"(d[2]), "=f"(d[3])
        : "r"(a[0]), "r"(a[1]), "r"(a[2]), "r"(a[3]),
          "r"(b[0]), "r"(b[1]),
          "f"(c[0]), "f"(c[1]), "f"(c[2]), "f"(c[3]));
}

// ============================================================================
// Kernel 0: build PAIRED fragment images (unchanged from R11).
// ============================================================================
__global__ void prep_kernel(const float* __restrict__ W1, const float* __restrict__ W2,
                            const float* __restrict__ W3, const float* __restrict__ U) {
    __half* gh = (__half*)g_wfrag;
    int idx = blockIdx.x * 256 + threadIdx.x;
    if (idx < 65536) {                    // W2 [256k x 256n]
        int k = idx >> 8, n = idx & 255;
        int chunk = k >> 5, ks = (k >> 4) & 1, kl = k & 15;
        int b_idx = kl >> 3, q = (kl & 7) >> 1, par = kl & 1;
        int wn = n >> 5, nt = (n >> 3) & 3, g = n & 7;
        int ntp = nt >> 1, sub = nt & 1;
        int slot4 = chunk * 1024 + ((ks * 8 + wn) * 2 + ntp) * 32 + g * 4 + q;
        gh[slot4 * 8 + sub * 4 + b_idx * 2 + par] = __float2half_rn(W2[idx]);
    } else if (idx < 69632) {             // W1 [16k x 256n]
        int t = idx - 65536;
        int k = t >> 8, n = t & 255;
        int b_idx = k >> 3, q = (k & 7) >> 1, par = k & 1;
        int wn = n >> 5, nt = (n >> 3) & 3, g = n & 7;
        int ntp = nt >> 1, sub = nt & 1;
        int slot4 = (wn * 2 + ntp) * 32 + g * 4 + q;
        gh[65536 + slot4 * 8 + sub * 4 + b_idx * 2 + par] = __float2half_rn(W1[t]);
    } else if (idx < 73728) {             // W3 [256k x 16n]
        int t = idx - 69632;
        int k = t >> 4, n = t & 15;
        int ks = k >> 4, kl = k & 15;
        int b_idx = kl >> 3, q = (kl & 7) >> 1, par = kl & 1;
        int nt = n >> 3, g = n & 7;
        int slot = (ks * 2 + nt) * 32 + g * 4 + q;
        gh[69632 + slot * 4 + b_idx * 2 + par] = __float2half_rn(W3[t]);
    } else if (idx < 74752) {             // ufA: kk-paired tf32 frags (z@U)
        int t = idx - 73728;
        int lane = t & 31, nt = (t >> 5) & 1, kk = t >> 6;
        int g = lane >> 2, q = lane & 3;
        int b4 = ((kk >> 1) * 2 + nt) * 32 + lane;
        g_ufA[b4 * 4 + (kk & 1) * 2]     = nan0(U[(kk * 8 + q) * RR + nt * 8 + g]);
        g_ufA[b4 * 4 + (kk & 1) * 2 + 1] = nan0(U[(kk * 8 + q + 4) * RR + nt * 8 + g]);
    } else if (idx < 75776) {             // ufB: nt-paired tf32 frags (cs@Ut)
        int t = idx - 74752;
        int lane = t & 31, ntt = (t >> 5) & 15, ks = t >> 9;
        int g = lane >> 2, q = lane & 3;
        int wnb = ntt >> 2, ntl = ntt & 3, ntp = ntl >> 1, sub = ntl & 1;
        int b4 = (ks * 8 + wnb * 2 + ntp) * 32 + lane;
        g_ufB[b4 * 4 + sub * 2]     = nan0(U[(ntt * 8 + g) * RR + ks * 8 + q]);
        g_ufB[b4 * 4 + sub * 2 + 1] = nan0(U[(ntt * 8 + g) * RR + ks * 8 + q + 4]);
    }
}

// ============================================================================
// Fused kernel: MLP (fp16 mma, f16 accumulate) + dynamics (tf32 mma).
// 64 rows/CTA, 512 threads, 2 CTAs/SM.
// ============================================================================
__global__ void __launch_bounds__(512, 2) fused_kernel(
    const float* __restrict__ pt, const float* __restrict__ z,
    const float* __restrict__ dt_norm_g, const float* __restrict__ U,
    const float* __restrict__ b1, const float* __restrict__ b2,
    const float* __restrict__ b3, float* __restrict__ out) {
    extern __shared__ char smc[];
    __shared__ uint32_t b1p[128], b2p[128];   // packed f16x2 bias pairs
    __shared__ float b3s[16], cn2s[16];

    const int tid = threadIdx.x;
    const int wid = tid >> 5, lane = tid & 31;
    const int g = lane >> 2, q = lane & 3;
    const int r0 = blockIdx.x * MTILE;
    const uint32_t sb = smem_u32(smc);
    const char* gw = (const char*)g_wfrag;

    // group 0: W1 frags + W3 frags
    cpa16(sb + OFF_W1F + tid * 16, gw + 131072 + tid * 16);
    cpa16(sb + OFF_W3F + tid * 16, gw + 139264 + tid * 16);
    cpcommit();
    // groups 1,2: W2 chunks 0,1
#pragma unroll
    for (int c = 0; c < 2; c++) {
#pragma unroll
        for (int i = 0; i < 2; i++) {
            int idx = tid + i * 512;
            cpa16(sb + OFF_RING + c * 16384 + idx * 16, gw + (size_t)c * 16384 + idx * 16);
        }
        cpcommit();
    }

    // --- stage x as fp16 A-frags (nan0) ---
    __half* xf = (__half*)(smc + OFF_XF);
#pragma unroll
    for (int i = 0; i < 2; i++) {
        int idx = tid + i * 512;
        int r = idx >> 4, c = idx & 15;
        float v = nan0(pt[(size_t)(r0 + r) * GD + c]);
        int rr = r & 15, rb = r >> 4;
        int gg = rr & 7, hi8 = rr >> 3;
        int qq = (c & 7) >> 1, par = c & 1;
        int a_idx = ((c >= 8) ? 2 : 0) + hi8;
        int ln = gg * 4 + qq;
        xf[(rb * 32 + ln) * 8 + a_idx * 2 + par] = __float2half_rn(v);
    }
    if (tid < 128) {
        b1p[tid] = packh(b1[2 * tid], b1[2 * tid + 1]);
        b2p[tid] = packh(b2[2 * tid], b2[2 * tid + 1]);
    }
    if (tid < 16) {
        b3s[tid] = b3[tid];
        float s = 0.f;
        for (int j = 0; j < ZD; j++) {
            float u = nan0(U[j * RR + tid]);
            s += u * u;
        }
        cn2s[tid] = s;
    }
    cpwait<2>();     // W1/W3 ready; chunks 0,1 in flight
    __syncthreads();

    const int wm = wid >> 3, wn = wid & 7;   // 2 x 8 warps (GEMM1/2)

    // ================= GEMM1: h1 = silu(x @ W1 + b1) -> h1 A-frags =========
#pragma unroll
    for (int mt = 0; mt < 2; mt++) {
        int rb = wm * 2 + mt;
        uint4 Av = *(const uint4*)(smc + OFF_XF + (rb * 32 + lane) * 16);
        uint32_t A[4] = {Av.x, Av.y, Av.z, Av.w};
#pragma unroll
        for (int ntp = 0; ntp < 2; ntp++) {
            uint4 Bp = *(const uint4*)(smc + OFF_W1F + ((wn * 2 + ntp) * 32 + lane) * 16);
            uint32_t d0[2] = {0u, 0u}, d1[2] = {0u, 0u};
            mma16h(d0, A, Bp.x, Bp.y);
            mma16h(d1, A, Bp.z, Bp.w);
            uint32_t bias0 = b1p[(wn * 4 + 2 * ntp) * 4 + q];
            uint32_t bias1 = b1p[(wn * 4 + 2 * ntp + 1) * 4 + q];
            int kk = wn * 2 + ntp;
            uint4 pk;
            pk.x = silu16(addh2(d0[0], bias0));
            pk.y = silu16(addh2(d0[1], bias0));
            pk.z = silu16(addh2(d1[0], bias1));
            pk.w = silu16(addh2(d1[1], bias1));
            *(uint4*)(smc + OFF_H1F + ((rb * 16 + kk) * 32 + lane) * 16) = pk;
        }
    }
    __syncthreads();

    // ================= GEMM2: h2 = silu(h1 @ W2 + b2), 8 chunks K=32 =======
    uint32_t acc[2][4][2];
#pragma unroll
    for (int mt = 0; mt < 2; mt++)
#pragma unroll
        for (int nt = 0; nt < 4; nt++) {
            acc[mt][nt][0] = 0u;
            acc[mt][nt][1] = 0u;
        }

    for (int c = 0; c < 8; c++) {
        if (c == 7) cpwait<0>(); else cpwait<1>();
        __syncthreads();
        if (c + 2 < 8) {
            int j = c + 2;
            int slot = j - (j / 3) * 3;
#pragma unroll
            for (int i = 0; i < 2; i++) {
                int idx = tid + i * 512;
                cpa16(sb + OFF_RING + slot * 16384 + idx * 16,
                      gw + (size_t)j * 16384 + idx * 16);
            }
            cpcommit();
        }
        const char* wb = smc + OFF_RING + (c - (c / 3) * 3) * 16384;
        // prefetch ALL A-frags for this chunk (4 x LDS.128) before the mma burst
        uint4 Ar[2][2];
#pragma unroll
        for (int ks = 0; ks < 2; ks++)
#pragma unroll
            for (int mt = 0; mt < 2; mt++)
                Ar[ks][mt] = *(const uint4*)(smc + OFF_H1F +
                                (((wm * 2 + mt) * 16 + c * 2 + ks) * 32 + lane) * 16);
#pragma unroll
        for (int ks = 0; ks < 2; ks++) {
            uint32_t A0[4] = {Ar[ks][0].x, Ar[ks][0].y, Ar[ks][0].z, Ar[ks][0].w};
            uint32_t A1[4] = {Ar[ks][1].x, Ar[ks][1].y, Ar[ks][1].z, Ar[ks][1].w};
#pragma unroll
            for (int ntp = 0; ntp < 2; ntp++) {
                uint4 Bp = *(const uint4*)(wb + (((ks * 8 + wn) * 2 + ntp) * 32 + lane) * 16);
                mma16h(acc[0][2 * ntp],     A0, Bp.x, Bp.y);
                mma16h(acc[1][2 * ntp],     A1, Bp.x, Bp.y);
                mma16h(acc[0][2 * ntp + 1], A0, Bp.z, Bp.w);
                mma16h(acc[1][2 * ntp + 1], A1, Bp.z, Bp.w);
            }
        }
    }
    __syncthreads();   // ring fully consumed

    // --- issue z load into (dead) ring region: zs stride 132 (inputs finite)
    {
        float* zs = (float*)(smc + OFF_ZS);
#pragma unroll
        for (int i = 0; i < 4; i++) {
            int idx = tid + i * 512;                // 2048 x float4
            int row = idx >> 5, c4 = (idx & 31) << 2;
            cpa16(smem_u32(&zs[row * 132 + c4]), &z[(size_t)(r0 + row) * ZD + c4]);
        }
        cpcommit();
    }

    // epilogue -> h2 A-frags (overlay OFF_H1F), f16 bias+silu, paired STS.128
#pragma unroll
    for (int mt = 0; mt < 2; mt++) {
        int rb = wm * 2 + mt;
#pragma unroll
        for (int ntp = 0; ntp < 2; ntp++) {
            uint32_t bias0 = b2p[(wn * 4 + 2 * ntp) * 4 + q];
            uint32_t bias1 = b2p[(wn * 4 + 2 * ntp + 1) * 4 + q];
            int kk = wn * 2 + ntp;
            uint4 pk;
            pk.x = silu16(addh2(acc[mt][2 * ntp][0], bias0));
            pk.y = silu16(addh2(acc[mt][2 * ntp][1], bias0));
            pk.z = silu16(addh2(acc[mt][2 * ntp + 1][0], bias1));
            pk.w = silu16(addh2(acc[mt][2 * ntp + 1][1], bias1));
            *(uint4*)(smc + OFF_H1F + ((rb * 16 + kk) * 32 + lane) * 16) = pk;
        }
    }
    __syncthreads();

    // ================= GEMM3: h = h2 @ W3 (K-split 2 x N-split 2, fp32 acc) =
    float* hp = (float*)(smc + OFF_HP);   // [2][64][20] fp32 partials (over XF+W1F)
    {
        int rb = wid & 3, wk = (wid >> 2) & 1, nt3 = wid >> 3;
        float a3[4] = {0.f, 0.f, 0.f, 0.f};
#pragma unroll
        for (int ksl = 0; ksl < 8; ksl++) {
            int kk = wk * 8 + ksl;
            uint4 Av = *(const uint4*)(smc + OFF_H1F + ((rb * 16 + kk) * 32 + lane) * 16);
            uint32_t A[4] = {Av.x, Av.y, Av.z, Av.w};
            uint2 Bv = *(const uint2*)(smc + OFF_W3F + ((kk * 2 + nt3) * 32 + lane) * 8);
            uint32_t B[2] = {Bv.x, Bv.y};
            mma16(a3, A, B, a3);
        }
        int c0 = nt3 * 8 + 2 * q;
        *(float2*)&hp[(wk * 64 + rb * 16 + g) * 20 + c0]     = make_float2(a3[0], a3[1]);
        *(float2*)&hp[(wk * 64 + rb * 16 + g + 8) * 20 + c0] = make_float2(a3[2], a3[3]);
    }
    __syncthreads();   // hp ready; h2f + W3F reads complete

    // --- issue ufA/ufB loads into dead h2f / W3F regions ---
    cpa16(sb + OFF_UFA + tid * 16, (const char*)g_ufA + tid * 16);
    cpa16(sb + OFF_UFB + tid * 16, (const char*)g_ufB + tid * 16);
    cpcommit();

    // ================= per-row epilogue: lamg, d -> smem =================
    float* ds = (float*)(smc + OFF_DS);
    float* lg = (float*)(smc + OFF_LG);
    if (tid < 64) {
        int row = tid;
        float s[16], fro2 = 0.f;
#pragma unroll
        for (int r = 0; r < 16; r++) {
            float v = b3s[r] + hp[row * 20 + r] + hp[(64 + row) * 20 + r];
            float sr = 2.f / (1.f + __expf(-v));
            s[r] = sr;
            fro2 += sr * sr * cn2s[r];
        }
        float fro = sqrtf(fro2);
        float scale = fminf(2.2627416997969522f / fmaxf(fro, 1e-9f), 1.f);

        float v = dt_norm_g[r0 + row];
        if (isnan(v)) v = 0.f;
        v = fminf(fmaxf(v, 0.f), 1.f);
        float logdt = fminf(-3.f + v * 11.f, 2.7781512503836436f);   // log10(600)
        float dt = fmaxf(expf(logdt * 2.302585092994046f), 1e-30f);
        float lamg = expf(-0.1f * dt);
        lg[row] = lamg;
#pragma unroll
        for (int r = 0; r < 16; r++) {
            float ss = s[r] * scale;
            float lp = expf(-ss * ss * dt) * lamg;
            ds[row * 20 + r] = lp - lamg;
        }
    }
    cpwait<0>();       // z + ufA/ufB landed
    __syncthreads();

    const float* zs = (const float*)(smc + OFF_ZS);
    float* cs = (float*)(smc + OFF_CS);
    const char* ufA = smc + OFF_UFA;
    const char* ufB = smc + OFF_UFB;

    // ===== GEMM A: cs[row][r] = d[row][r] * (z @ U)[row][r]  (8 warps) =====
    if (wid < 8) {
        int mt = wid >> 1, nt = wid & 1;
        int rbase = mt * 16, cbase = nt * 8;
        float accA[4] = {0.f, 0.f, 0.f, 0.f};
#pragma unroll
        for (int kp = 0; kp < 8; kp++) {
            uint4 Bv = *(const uint4*)(ufA + ((kp * 2 + nt) * 32 + lane) * 16);
#pragma unroll
            for (int sub = 0; sub < 2; sub++) {
                int k0 = (kp * 2 + sub) * 8;
                uint32_t a[4] = {
                    fbits(zs[(rbase + g) * 132 + k0 + q]),
                    fbits(zs[(rbase + g + 8) * 132 + k0 + q]),
                    fbits(zs[(rbase + g) * 132 + k0 + q + 4]),
                    fbits(zs[(rbase + g + 8) * 132 + k0 + q + 4])};
                uint32_t b[2] = {sub ? Bv.z : Bv.x, sub ? Bv.w : Bv.y};
                mma8(accA, a, b, accA);
            }
        }
        int row0 = rbase + g, row1 = rbase + g + 8;
        int c0 = cbase + 2 * q, c1 = c0 + 1;
        cs[row0 * 20 + c0] = accA[0] * ds[row0 * 20 + c0];
        cs[row0 * 20 + c1] = accA[1] * ds[row0 * 20 + c1];
        cs[row1 * 20 + c0] = accA[2] * ds[row1 * 20 + c0];
        cs[row1 * 20 + c1] = accA[3] * ds[row1 * 20 + c1];
    }
    __syncthreads();

    // ===== GEMM B + identity, direct to global (16 warps) =====
    {
        int mt = wid & 3, wnb = wid >> 2;     // mt: 16-row tile, wnb: 32-col group
        int rbase = mt * 16;
        float accB[4][4];
#pragma unroll
        for (int nt = 0; nt < 4; nt++)
#pragma unroll
            for (int i = 0; i < 4; i++) accB[nt][i] = 0.f;
#pragma unroll
        for (int ks = 0; ks < 2; ks++) {
            int k0 = ks * 8;
            uint32_t a[4] = {
                fbits(cs[(rbase + g) * 20 + k0 + q]),
                fbits(cs[(rbase + g + 8) * 20 + k0 + q]),
                fbits(cs[(rbase + g) * 20 + k0 + q + 4]),
                fbits(cs[(rbase + g + 8) * 20 + k0 + q + 4])};
#pragma unroll
            for (int ntp = 0; ntp < 2; ntp++) {
                uint4 Bp = *(const uint4*)(ufB + ((ks * 8 + wnb * 2 + ntp) * 32 + lane) * 16);
                uint32_t B0[2] = {Bp.x, Bp.y}, B1[2] = {Bp.z, Bp.w};
                mma8(accB[2 * ntp],     a, B0, accB[2 * ntp]);
                mma8(accB[2 * ntp + 1], a, B1, accB[2 * ntp + 1]);
            }
        }
        int row0 = rbase + g, row1 = rbase + g + 8;
        float l0 = lg[row0], l1 = lg[row1];
        size_t gr0 = (size_t)(r0 + row0) * ZD, gr1 = (size_t)(r0 + row1) * ZD;
#pragma unroll
        for (int nt = 0; nt < 4; nt++) {
            int cb = (wnb * 4 + nt) * 8;
            int c0 = cb + 2 * q;
            float2 z0 = *(const float2*)&zs[row0 * 132 + c0];
            float2 o0;
            o0.x = l0 * z0.x + accB[nt][0];
            o0.y = l0 * z0.y + accB[nt][1];
            *(float2*)&out[gr0 + c0] = o0;
            float2 z1 = *(const float2*)&zs[row1 * 132 + c0];
            float2 o1;
            o1.x = l1 * z1.x + accB[nt][2];
            o1.y = l1 * z1.y + accB[nt][3];
            *(float2*)&out[gr1 + c0] = o1;
        }
    }
}

extern "C" void kernel_launch(void* const* d_in, const int* in_sizes, int n_in,
                              void* d_out, int out_size) {
    const float* pt      = (const float*)d_in[0];
    const float* z       = (const float*)d_in[1];
    const float* dt_norm = (const float*)d_in[2];
    const float* base_U  = (const float*)d_in[3];
    const float* W1      = (const float*)d_in[4];
    const float* b1      = (const float*)d_in[5];
    const float* W2      = (const float*)d_in[6];
    const float* b2      = (const float*)d_in[7];
    const float* W3      = (const float*)d_in[8];
    const float* b3      = (const float*)d_in[9];
    float* out = (float*)d_out;

    cudaFuncSetAttribute(fused_kernel, cudaFuncAttributeMaxDynamicSharedMemorySize, SMEM_BYTES);

    prep_kernel<<<296, 256>>>(W1, W2, W3, base_U);
    fused_kernel<<<NBLK, 512, SMEM_BYTES>>>(pt, z, dt_norm, base_U, b1, b2, b3, out);
}